// round 9
// baseline (speedup 1.0000x reference)
#include <cuda_runtime.h>
#include <cuda_fp16.h>
#include <cstdint>
#include <math.h>

// ---------------- problem constants ----------------
#define BATCH 4096
#define LSEQ  28
#define VOCAB 32000
#define DIM   300
#define BW_E  8704            // per-batch row: 300 front pad + 8400 data + 4 back pad
#define KPAD_F 128
#define K1    1504            // conv1/conv2 GEMM K (1500 padded)
#define K3    3008            // conv3 GEMM K (3000 padded)
#define BW_H1 3904            // 13*300 + 4
#define BW_H2 3008            // 5*600 + 8
#define L1o   13
#define C1    300
#define L2o   5
#define C2    600
#define C3    100
#define M1    (BATCH*L1o)     // 53248 = 416*128
#define M2    (BATCH*L2o)     // 20480 = 160*128
#define NPAIRS 8386560
#define HOUT  (BATCH*C3)

// ---------------- scratch ----------------
__device__ __half g_Eh[(size_t)BATCH*BW_E + 64];
__device__ __half g_El[(size_t)BATCH*BW_E + 64];
__device__ __half g_W1h[384*K1], g_W1l[384*K1];
__device__ __half g_W2h[640*K1], g_W2l[640*K1];
__device__ __half g_W3h[128*K3], g_W3l[128*K3];
__device__ float g_h1[(size_t)M1*C1];
__device__ float g_h2[(size_t)M2*C2];
__device__ __half g_h1h[(size_t)BATCH*BW_H1 + 64], g_h1l[(size_t)BATCH*BW_H1 + 64];
__device__ __half g_h2h[(size_t)BATCH*BW_H2 + 64], g_h2l[(size_t)BATCH*BW_H2 + 64];
__device__ float g_final[BATCH*C3];
__device__ __half g_Fnh[BATCH*KPAD_F], g_Fnl[BATCH*KPAD_F];
__device__ float g_scales[VOCAB];
__device__ float g_mean1[C1], g_istd1[C1];
__device__ float g_mean2[C2], g_istd2[C2];
__device__ float g_part[32*640*2];

// ---------------- embedding renorm scales ----------------
__global__ void k_scales(const float* __restrict__ emb) {
    int warp = (blockIdx.x * blockDim.x + threadIdx.x) >> 5;
    int lane = threadIdx.x & 31;
    if (warp >= VOCAB) return;
    const float* row = emb + (size_t)warp * DIM;
    float s = 0.f;
    for (int d = lane; d < DIM; d += 32) { float v = row[d]; s += v * v; }
    #pragma unroll
    for (int o = 16; o; o >>= 1) s += __shfl_xor_sync(0xffffffffu, s, o);
    if (lane == 0) g_scales[warp] = fminf(1.f, 1.f / (sqrtf(s) + 1e-7f));
}

// ---------------- gather into position-major E_T (+ fp16 split, + pads) ----------------
__global__ void k_gather(const int* __restrict__ x, const float* __restrict__ emb) {
    __shared__ int   tok[LSEQ];
    __shared__ float sc[LSEQ];
    int b = blockIdx.x, t = threadIdx.x;
    bool is64 = (x[1] == 0 && x[3] == 0 && x[5] == 0 && x[7] == 0);
    if (t < LSEQ) {
        int v = is64 ? x[(b * LSEQ + t) * 2] : x[b * LSEQ + t];
        tok[t] = v;
        sc[t]  = g_scales[v];
    }
    __syncthreads();
    __half* dH = g_Eh + (size_t)b * BW_E;
    __half* dL = g_El + (size_t)b * BW_E;
    const __half z = __float2half_rn(0.f);
    for (int i = t; i < 304; i += blockDim.x) {
        int o = (i < 300) ? i : (8400 + i);
        dH[o] = z; dL[o] = z;
    }
    for (int i = t; i < DIM * LSEQ; i += blockDim.x) {
        int l = i / DIM, ci = i - l * DIM;
        float v = emb[(size_t)tok[l] * DIM + ci] * sc[l];
        __half h = __float2half_rn(v);
        dH[300 + i] = h;
        dL[300 + i] = __float2half_rn(v - __half2float(h));
    }
}

// ---------------- weight prep ----------------
__global__ void k_prep_w(const float* __restrict__ w1, const float* __restrict__ w2,
                         const float* __restrict__ w3) {
    const int n1 = 384 * K1, n2 = 640 * K1, n3 = 128 * K3;
    int total = n1 + n2 + n3;
    for (int idx = blockIdx.x * blockDim.x + threadIdx.x; idx < total; idx += gridDim.x * blockDim.x) {
        int i = idx;
        if (i < n1) {
            int n = i / K1, k = i - n * K1;
            int kk = k / 300, ci = k - kk * 300;
            float v = (n < C1 && kk < 5) ? w1[n * 1500 + ci * 5 + kk] : 0.f;
            __half h = __float2half_rn(v);
            g_W1h[i] = h;
            g_W1l[i] = __float2half_rn(v - __half2float(h));
            continue;
        }
        i -= n1;
        if (i < n2) {
            int n = i / K1, k = i - n * K1;
            int kk = k / 300, ci = k - kk * 300;
            float v = (n < C2 && kk < 5) ? w2[n * 1500 + ci * 5 + kk] : 0.f;
            __half h = __float2half_rn(v);
            g_W2h[i] = h;
            g_W2l[i] = __float2half_rn(v - __half2float(h));
            continue;
        }
        i -= n2;
        {
            int n = i / K3, k = i - n * K3;
            int kk = k / 600, ci = k - kk * 600;
            float v = (n < C3 && kk < 5) ? w3[n * 3000 + ci * 5 + kk] : 0.f;
            __half h = __float2half_rn(v);
            g_W3h[i] = h;
            g_W3l[i] = __float2half_rn(v - __half2float(h));
        }
    }
}

// ---------------- zero tail pads ----------------
__global__ void k_padzero() {
    int b = blockIdx.x * blockDim.x + threadIdx.x;
    const __half z = __float2half_rn(0.f);
    if (b < BATCH) {
        #pragma unroll
        for (int i = 0; i < 4; i++) {
            g_h1h[(size_t)b * BW_H1 + 3900 + i] = z;
            g_h1l[(size_t)b * BW_H1 + 3900 + i] = z;
        }
        #pragma unroll
        for (int i = 0; i < 8; i++) {
            g_h2h[(size_t)b * BW_H2 + 3000 + i] = z;
            g_h2l[(size_t)b * BW_H2 + 3000 + i] = z;
        }
    }
    if (b < 64) {
        g_Eh[(size_t)BATCH * BW_E + b]  = z;
        g_El[(size_t)BATCH * BW_E + b]  = z;
        g_h1h[(size_t)BATCH * BW_H1 + b] = z;
        g_h1l[(size_t)BATCH * BW_H1 + b] = z;
        g_h2h[(size_t)BATCH * BW_H2 + b] = z;
        g_h2l[(size_t)BATCH * BW_H2 + b] = z;
    }
}

// ---------------- BN stats ----------------
__global__ void k_bnstat_p(const float* __restrict__ h, int M, int C) {
    int lane = threadIdx.x & 31;
    int w = threadIdx.x >> 5;
    int c = blockIdx.x * 32 + lane;
    int chunk = blockIdx.y;
    int rpc = M >> 5;
    float s = 0.f, s2 = 0.f;
    if (c < C) {
        int r1 = (chunk + 1) * rpc;
        for (int r = chunk * rpc + w; r < r1; r += 8) {
            float v = h[(size_t)r * C + c];
            s += v; s2 += v * v;
        }
    }
    __shared__ float sh[8][32][2];
    sh[w][lane][0] = s; sh[w][lane][1] = s2;
    __syncthreads();
    if (threadIdx.x < 32) {
        float S = 0.f, S2 = 0.f;
        #pragma unroll
        for (int i = 0; i < 8; i++) { S += sh[i][threadIdx.x][0]; S2 += sh[i][threadIdx.x][1]; }
        int cc = blockIdx.x * 32 + threadIdx.x;
        if (cc < C) {
            g_part[(chunk * 640 + cc) * 2 + 0] = S;
            g_part[(chunk * 640 + cc) * 2 + 1] = S2;
        }
    }
}

__global__ void k_bnstat_r(int C, float invN, float* __restrict__ mean, float* __restrict__ istd) {
    int c = blockIdx.x * blockDim.x + threadIdx.x;
    if (c >= C) return;
    float S = 0.f, S2 = 0.f;
    for (int ch = 0; ch < 32; ch++) {
        S  += g_part[(ch * 640 + c) * 2 + 0];
        S2 += g_part[(ch * 640 + c) * 2 + 1];
    }
    float m = S * invN;
    mean[c] = m;
    istd[c] = rsqrtf(S2 * invN - m * m + 1e-5f);
}

// ---------------- BN apply + ReLU + fp16 split into padded T layout ----------------
__global__ void k_bnapply(const float* __restrict__ h, __half* __restrict__ oh,
                          __half* __restrict__ ol,
                          const float* __restrict__ mean, const float* __restrict__ istd,
                          const float* __restrict__ gamma, const float* __restrict__ beta,
                          int M, int C, int lout, int pad) {
    size_t total = (size_t)M * C;
    size_t stride = (size_t)gridDim.x * blockDim.x;
    for (size_t idx = (size_t)blockIdx.x * blockDim.x + threadIdx.x; idx < total; idx += stride) {
        int m = (int)(idx / C), c = (int)(idx - (size_t)m * C);
        float v = (h[idx] - mean[c]) * istd[c] * gamma[c] + beta[c];
        v = fmaxf(v, 0.f);
        size_t off = idx + (size_t)pad * (m / lout);
        __half hi = __float2half_rn(v);
        oh[off] = hi;
        ol[off] = __float2half_rn(v - __half2float(hi));
    }
}

// ---------------- row-normalize final -> fp16 hi/lo ----------------
__global__ void k_norm() {
    int gw = (blockIdx.x * blockDim.x + threadIdx.x) >> 5;
    int lane = threadIdx.x & 31;
    if (gw >= BATCH) return;
    const float* f = g_final + gw * C3;
    float s = 0.f;
    for (int c = lane; c < C3; c += 32) { float v = f[c]; s += v * v; }
    #pragma unroll
    for (int o = 16; o; o >>= 1) s += __shfl_xor_sync(0xffffffffu, s, o);
    float n = sqrtf(s);
    __half* oh = g_Fnh + gw * KPAD_F;
    __half* ol = g_Fnl + gw * KPAD_F;
    for (int c = lane; c < C3; c += 32) {
        float v = f[c] / n;
        __half h = __float2half_rn(v);
        oh[c] = h;
        ol[c] = __float2half_rn(v - __half2float(h));
    }
    for (int c = C3 + lane; c < KPAD_F; c += 32) {
        oh[c] = __float2half_rn(0.f);
        ol[c] = __float2half_rn(0.f);
    }
}

// ================= HMMA GEMM machinery (split-fp16, swizzled smem) =================
#define GBM 128
#define GBK 32
#define GSTAGES 3
#define MSZ (128*32)
#define STG (4*MSZ)

__device__ __forceinline__ void cp16(__half* dst, const __half* src) {
    unsigned a = (unsigned)__cvta_generic_to_shared(dst);
    asm volatile("cp.async.cg.shared.global [%0], [%1], 16;\n" :: "r"(a), "l"(src));
}
__device__ __forceinline__ void ldm4(unsigned* r, const __half* p) {
    unsigned a = (unsigned)__cvta_generic_to_shared(p);
    asm volatile("ldmatrix.sync.aligned.m8n8.x4.shared.b16 {%0,%1,%2,%3}, [%4];\n"
                 : "=r"(r[0]), "=r"(r[1]), "=r"(r[2]), "=r"(r[3]) : "r"(a));
}
__device__ __forceinline__ void mma16816(float* d, const unsigned* a, const unsigned* b) {
    asm volatile("mma.sync.aligned.m16n8k16.row.col.f32.f16.f16.f32 "
                 "{%0,%1,%2,%3}, {%4,%5,%6,%7}, {%8,%9}, {%0,%1,%2,%3};\n"
                 : "+f"(d[0]), "+f"(d[1]), "+f"(d[2]), "+f"(d[3])
                 : "r"(a[0]), "r"(a[1]), "r"(a[2]), "r"(a[3]), "r"(b[0]), "r"(b[1]));
}
__device__ __forceinline__ int swz(int row, int chunk) {
    return row * 32 + ((chunk ^ ((row >> 1) & 3)) << 3);
}

// A rows: ptr = Ah + (row/LA)*bwA + (row%LA)*600 + k
template<int LA, bool THREE>
__device__ __forceinline__ void load_stage(__half* dst,
        const __half* Ah, const __half* Al,
        const __half* Bh, const __half* Bl,
        int i0, int j0, int kc, int bwA, int bwB, int t) {
    #pragma unroll
    for (int q = 0; q < 4; q++) {
        int idx = t + q * 128;
        int row = idx >> 2, c = idx & 3;
        int so = swz(row, c);
        int ra = i0 + row;
        int ba = ra / LA, la = ra - ba * LA;
        size_t goA = (size_t)ba * bwA + la * 600 + kc + c * 8;
        size_t goB = (size_t)(j0 + row) * bwB + kc + c * 8;
        cp16(dst + 0 * MSZ + so, Ah + goA);
        if (THREE) cp16(dst + 1 * MSZ + so, Al + goA);
        cp16(dst + 2 * MSZ + so, Bh + goB);
        cp16(dst + 3 * MSZ + so, Bl + goB);
    }
}

template<int LA, bool THREE>
__device__ __forceinline__ void gemm_core(
        const __half* Ah, const __half* Al,
        const __half* Bh, const __half* Bl,
        int i0, int j0, int bwA, int bwB, int kIters,
        __half* sm, int t, float acc[4][8][4]) {
    int lane = t & 31, wid = t >> 5;
    int wm = wid & 1, wn = wid >> 1;      // 2x2 warp grid, 64x64 per warp
    int lr = lane & 15, lc = (lane >> 4) << 3;

    #pragma unroll
    for (int s = 0; s < GSTAGES - 1; s++) {
        if (s < kIters) load_stage<LA, THREE>(sm + s * STG, Ah, Al, Bh, Bl, i0, j0, s * GBK, bwA, bwB, t);
        asm volatile("cp.async.commit_group;\n");
    }
    for (int it = 0; it < kIters; it++) {
        asm volatile("cp.async.wait_group %0;\n" :: "n"(GSTAGES - 2));
        __syncthreads();
        int nxt = it + GSTAGES - 1;
        if (nxt < kIters) load_stage<LA, THREE>(sm + (nxt % GSTAGES) * STG, Ah, Al, Bh, Bl, i0, j0, nxt * GBK, bwA, bwB, t);
        asm volatile("cp.async.commit_group;\n");

        const __half* buf = sm + (it % GSTAGES) * STG;
        const __half* sAh = buf;
        const __half* sAl = buf + MSZ;
        const __half* sBh = buf + 2 * MSZ;
        const __half* sBl = buf + 3 * MSZ;

        #pragma unroll
        for (int ks = 0; ks < GBK; ks += 16) {
            unsigned ah[4][4], al[4][4], bh[8][2], bl[8][2];
            int cl = (ks + lc) >> 3;
            #pragma unroll
            for (int mt = 0; mt < 4; mt++) {
                int rA = wm * 64 + mt * 16 + lr;
                ldm4(ah[mt], sAh + swz(rA, cl));
                if (THREE) ldm4(al[mt], sAl + swz(rA, cl));
            }
            #pragma unroll
            for (int bt = 0; bt < 4; bt++) {
                int rB = wn * 64 + bt * 16 + lr;
                unsigned r4[4];
                ldm4(r4, sBh + swz(rB, cl));
                bh[2 * bt][0] = r4[0]; bh[2 * bt][1] = r4[2];
                bh[2 * bt + 1][0] = r4[1]; bh[2 * bt + 1][1] = r4[3];
                ldm4(r4, sBl + swz(rB, cl));
                bl[2 * bt][0] = r4[0]; bl[2 * bt][1] = r4[2];
                bl[2 * bt + 1][0] = r4[1]; bl[2 * bt + 1][1] = r4[3];
            }
            #pragma unroll
            for (int mt = 0; mt < 4; mt++)
                #pragma unroll
                for (int nt = 0; nt < 8; nt++) {
                    mma16816(acc[mt][nt], ah[mt], bh[nt]);
                    mma16816(acc[mt][nt], ah[mt], bl[nt]);
                    if (THREE) mma16816(acc[mt][nt], al[mt], bh[nt]);
                }
        }
        __syncthreads();
    }
}

// ---------------- hidden Gram (128x128 tiles, 3-term), triu-packed ----------------
__global__ __launch_bounds__(128, 2)
void k_gram_t(const __half* __restrict__ Xhi, const __half* __restrict__ Xlo,
              int ldk, int kIters, float* __restrict__ out) {
    extern __shared__ __half sm[];
    int p = blockIdx.x;
    int ti = 0, rem = 32;
    while (p >= rem) { p -= rem; rem--; ti++; }
    int tj = ti + p;
    const int i0 = ti * GBM, j0 = tj * GBM;

    int t = threadIdx.x;
    float acc[4][8][4];
    #pragma unroll
    for (int mt = 0; mt < 4; mt++)
        #pragma unroll
        for (int nt = 0; nt < 8; nt++)
            #pragma unroll
            for (int e = 0; e < 4; e++) acc[mt][nt][e] = 0.f;

    gemm_core<1, true>(Xhi, Xlo, Xhi, Xlo, i0, j0, ldk, ldk, kIters, sm, t, acc);

    int lane = t & 31, wid = t >> 5;
    int wm = wid & 1, wn = wid >> 1;
    int r = lane >> 2, cp = (lane & 3) * 2;
    #pragma unroll
    for (int mt = 0; mt < 4; mt++) {
        #pragma unroll
        for (int h = 0; h < 2; h++) {
            int i = i0 + wm * 64 + mt * 16 + r + h * 8;
            int base = i * (8191 - i) / 2 - i - 1;
            #pragma unroll
            for (int nt = 0; nt < 8; nt++) {
                int j = j0 + wn * 64 + nt * 8 + cp;
                if (j > i)     out[base + j]     = acc[mt][nt][2 * h + 0];
                if (j + 1 > i) out[base + j + 1] = acc[mt][nt][2 * h + 1];
            }
        }
    }
}

// ================= big input Gram: 256x128 tiles, 2-term fp16, 4-stage =================
#define BSTG  4
#define A2SZ  (256*32)
#define B2SZ  (128*32)
#define STG2  (A2SZ + 2*B2SZ)          // 16384 halves = 32KB
#define BG_SMEM (BSTG*STG2*2)          // 131072 bytes

__device__ __forceinline__ void load_stage_big(__half* dst,
        const __half* __restrict__ Xh, const __half* __restrict__ Xl,
        int i0, int j0, int kc, int ldk, int t) {
    #pragma unroll
    for (int q = 0; q < 4; q++) {       // A hi: 256 rows
        int idx = t + q * 256;
        int row = idx >> 2, c = idx & 3;
        cp16(dst + swz(row, c), Xh + (size_t)(i0 + row) * ldk + kc + c * 8);
    }
    #pragma unroll
    for (int q = 0; q < 2; q++) {       // B hi + lo: 128 rows
        int idx = t + q * 256;
        int row = idx >> 2, c = idx & 3;
        size_t g = (size_t)(j0 + row) * ldk + kc + c * 8;
        cp16(dst + A2SZ + swz(row, c), Xh + g);
        cp16(dst + A2SZ + B2SZ + swz(row, c), Xl + g);
    }
}

__global__ __launch_bounds__(256, 1)
void k_gram_big(const __half* __restrict__ Xh, const __half* __restrict__ Xl,
                int ldk, int kIters, float* __restrict__ out) {
    extern __shared__ __half sm[];
    // tile map: M-tile ti (256 rows), N-tile index p within [2*ti, 32)
    int p = blockIdx.x, ti = 0, rem = 32;
    while (p >= rem) { p -= rem; rem -= 2; ti++; }
    const int i0 = ti * 256, j0 = ti * 256 + p * 128;

    int t = threadIdx.x, lane = t & 31, wid = t >> 5;
    int wm = wid & 3, wn = wid >> 2;    // 4(M) x 2(N) warp grid, 64x64 tiles
    int lr = lane & 15, lc = (lane >> 4) << 3;

    float acc[4][8][4];
    #pragma unroll
    for (int mt = 0; mt < 4; mt++)
        #pragma unroll
        for (int nt = 0; nt < 8; nt++)
            #pragma unroll
            for (int e = 0; e < 4; e++) acc[mt][nt][e] = 0.f;

    #pragma unroll
    for (int s = 0; s < BSTG - 1; s++) {
        if (s < kIters) load_stage_big(sm + s * STG2, Xh, Xl, i0, j0, s * GBK, ldk, t);
        asm volatile("cp.async.commit_group;\n");
    }
    for (int it = 0; it < kIters; it++) {
        asm volatile("cp.async.wait_group %0;\n" :: "n"(BSTG - 2));
        __syncthreads();
        int nxt = it + BSTG - 1;
        if (nxt < kIters) load_stage_big(sm + (nxt % BSTG) * STG2, Xh, Xl, i0, j0, nxt * GBK, ldk, t);
        asm volatile("cp.async.commit_group;\n");

        const __half* buf = sm + (it % BSTG) * STG2;
        const __half* sA  = buf;
        const __half* sBh = buf + A2SZ;
        const __half* sBl = buf + A2SZ + B2SZ;

        #pragma unroll
        for (int ks = 0; ks < GBK; ks += 16) {
            unsigned ah[4][4], bh[8][2], bl[8][2];
            int cl = (ks + lc) >> 3;
            #pragma unroll
            for (int mt = 0; mt < 4; mt++) {
                int rA = wm * 64 + mt * 16 + lr;
                ldm4(ah[mt], sA + swz(rA, cl));
            }
            #pragma unroll
            for (int bt = 0; bt < 4; bt++) {
                int rB = wn * 64 + bt * 16 + lr;
                unsigned r4[4];
                ldm4(r4, sBh + swz(rB, cl));
                bh[2 * bt][0] = r4[0]; bh[2 * bt][1] = r4[2];
                bh[2 * bt + 1][0] = r4[1]; bh[2 * bt + 1][1] = r4[3];
                ldm4(r4, sBl + swz(rB, cl));
                bl[2 * bt][0] = r4[0]; bl[2 * bt][1] = r4[2];
                bl[2 * bt + 1][0] = r4[1]; bl[2 * bt + 1][1] = r4[3];
            }
            #pragma unroll
            for (int mt = 0; mt < 4; mt++)
                #pragma unroll
                for (int nt = 0; nt < 8; nt++) {
                    mma16816(acc[mt][nt], ah[mt], bh[nt]);
                    mma16816(acc[mt][nt], ah[mt], bl[nt]);
                }
        }
        __syncthreads();
    }

    int r = lane >> 2, cp = (lane & 3) * 2;
    #pragma unroll
    for (int mt = 0; mt < 4; mt++) {
        #pragma unroll
        for (int h = 0; h < 2; h++) {
            int i = i0 + wm * 64 + mt * 16 + r + h * 8;
            int base = i * (8191 - i) / 2 - i - 1;
            #pragma unroll
            for (int nt = 0; nt < 8; nt++) {
                int j = j0 + wn * 64 + nt * 8 + cp;
                if (j > i)     out[base + j]     = acc[mt][nt][2 * h + 0];
                if (j + 1 > i) out[base + j + 1] = acc[mt][nt][2 * h + 1];
            }
        }
    }
}

// ---------------- conv GEMM: implicit im2col; MODE 0: bias; MODE 1: bias+tanh -> dst & out2 ----------------
template<int LA, int MODE>
__global__ __launch_bounds__(128, 2)
void k_conv_gemm(const __half* __restrict__ Ah, const __half* __restrict__ Al,
                 const __half* __restrict__ Bh, const __half* __restrict__ Bl,
                 int kIters, int bwA, int bwB, int Cout,
                 const float* __restrict__ bias, float* __restrict__ dst, float* __restrict__ out2) {
    extern __shared__ __half sm[];
    const int n0 = blockIdx.x * GBM, m0 = blockIdx.y * GBM;

    int t = threadIdx.x;
    float acc[4][8][4];
    #pragma unroll
    for (int mt = 0; mt < 4; mt++)
        #pragma unroll
        for (int nt = 0; nt < 8; nt++)
            #pragma unroll
            for (int e = 0; e < 4; e++) acc[mt][nt][e] = 0.f;

    gemm_core<LA, true>(Ah, Al, Bh, Bl, m0, n0, bwA, bwB, kIters, sm, t, acc);

    int lane = t & 31, wid = t >> 5;
    int wm = wid & 1, wn = wid >> 1;
    int r = lane >> 2, cp = (lane & 3) * 2;
    #pragma unroll
    for (int mt = 0; mt < 4; mt++) {
        #pragma unroll
        for (int h = 0; h < 2; h++) {
            int m = m0 + wm * 64 + mt * 16 + r + h * 8;
            #pragma unroll
            for (int nt = 0; nt < 8; nt++) {
                int n = n0 + wn * 64 + nt * 8 + cp;
                float a0 = acc[mt][nt][2 * h + 0];
                float a1 = acc[mt][nt][2 * h + 1];
                if (MODE == 0) {
                    if (n < Cout)     dst[(size_t)m * Cout + n]     = a0 + bias[n];
                    if (n + 1 < Cout) dst[(size_t)m * Cout + n + 1] = a1 + bias[n + 1];
                } else {
                    if (n < Cout) {
                        float v = tanhf(a0 + bias[n]);
                        dst[(size_t)m * Cout + n] = v;
                        out2[(size_t)m * Cout + n] = v;
                    }
                    if (n + 1 < Cout) {
                        float v = tanhf(a1 + bias[n + 1]);
                        dst[(size_t)m * Cout + n + 1] = v;
                        out2[(size_t)m * Cout + n + 1] = v;
                    }
                }
            }
        }
    }
}

// ---------------- launch ----------------
extern "C" void kernel_launch(void* const* d_in, const int* in_sizes, int n_in,
                              void* d_out, int out_size) {
    const int*   x   = (const int*)  d_in[0];
    const float* emb = (const float*)d_in[1];
    const float* w1  = (const float*)d_in[2];
    const float* b1  = (const float*)d_in[3];
    const float* w2  = (const float*)d_in[4];
    const float* b2  = (const float*)d_in[5];
    const float* w3  = (const float*)d_in[6];
    const float* b3  = (const float*)d_in[7];
    const float* g1  = (const float*)d_in[8];
    const float* be1 = (const float*)d_in[9];
    const float* g2  = (const float*)d_in[10];
    const float* be2 = (const float*)d_in[11];
    float* out = (float*)d_out;

    const int gemmSmem = GSTAGES * STG * 2;   // 98304 bytes
    cudaFuncSetAttribute(k_gram_t,          cudaFuncAttributeMaxDynamicSharedMemorySize, gemmSmem);
    cudaFuncSetAttribute(k_gram_big,        cudaFuncAttributeMaxDynamicSharedMemorySize, BG_SMEM);
    cudaFuncSetAttribute(k_conv_gemm<13,0>, cudaFuncAttributeMaxDynamicSharedMemorySize, gemmSmem);
    cudaFuncSetAttribute(k_conv_gemm<5,0>,  cudaFuncAttributeMaxDynamicSharedMemorySize, gemmSmem);
    cudaFuncSetAttribute(k_conv_gemm<1,1>,  cudaFuncAttributeMaxDynamicSharedMemorySize, gemmSmem);

    __half *eh, *el, *w1h, *w1l, *w2h, *w2l, *w3h, *w3l;
    __half *h1h, *h1l, *h2h, *h2l, *fh, *fl;
    float *h1p, *h2p, *finp, *m1p, *i1p, *m2p, *i2p;
    cudaGetSymbolAddress((void**)&eh,  g_Eh);
    cudaGetSymbolAddress((void**)&el,  g_El);
    cudaGetSymbolAddress((void**)&w1h, g_W1h);
    cudaGetSymbolAddress((void**)&w1l, g_W1l);
    cudaGetSymbolAddress((void**)&w2h, g_W2h);
    cudaGetSymbolAddress((void**)&w2l, g_W2l);
    cudaGetSymbolAddress((void**)&w3h, g_W3h);
    cudaGetSymbolAddress((void**)&w3l, g_W3l);
    cudaGetSymbolAddress((void**)&h1h, g_h1h);
    cudaGetSymbolAddress((void**)&h1l, g_h1l);
    cudaGetSymbolAddress((void**)&h2h, g_h2h);
    cudaGetSymbolAddress((void**)&h2l, g_h2l);
    cudaGetSymbolAddress((void**)&fh,  g_Fnh);
    cudaGetSymbolAddress((void**)&fl,  g_Fnl);
    cudaGetSymbolAddress((void**)&h1p, g_h1);
    cudaGetSymbolAddress((void**)&h2p, g_h2);
    cudaGetSymbolAddress((void**)&finp, g_final);
    cudaGetSymbolAddress((void**)&m1p, g_mean1);
    cudaGetSymbolAddress((void**)&i1p, g_istd1);
    cudaGetSymbolAddress((void**)&m2p, g_mean2);
    cudaGetSymbolAddress((void**)&i2p, g_istd2);

    k_scales<<<(VOCAB * 32 + 255) / 256, 256>>>(emb);
    k_gather<<<BATCH, 256>>>(x, emb);
    k_prep_w<<<1024, 256>>>(w1, w2, w3);
    k_padzero<<<16, 256>>>();

    // conv1: implicit-im2col GEMM
    {
        dim3 g(3, M1 / GBM);
        k_conv_gemm<13,0><<<g, 128, gemmSmem>>>(eh, el, w1h, w1l, (K1 + GBK - 1) / GBK, BW_E, K1, C1, b1, h1p, nullptr);
    }
    k_bnstat_p<<<dim3(10, 32), 256>>>(h1p, M1, C1);
    k_bnstat_r<<<2, 256>>>(C1, 1.f / M1, m1p, i1p);
    k_bnapply<<<2048, 256>>>(h1p, h1h, h1l, m1p, i1p, g1, be1, M1, C1, L1o, 4);

    // conv2
    {
        dim3 g(5, M2 / GBM);
        k_conv_gemm<5,0><<<g, 128, gemmSmem>>>(h1h, h1l, w2h, w2l, (K1 + GBK - 1) / GBK, BW_H1, K1, C2, b2, h2p, nullptr);
    }
    k_bnstat_p<<<dim3(19, 32), 256>>>(h2p, M2, C2);
    k_bnstat_r<<<3, 256>>>(C2, 1.f / M2, m2p, i2p);
    k_bnapply<<<2048, 256>>>(h2p, h2h, h2l, m2p, i2p, g2, be2, M2, C2, L2o, 8);

    // conv3 (+tanh) -> g_final and out[0:HOUT]
    {
        dim3 g(1, BATCH / GBM);
        k_conv_gemm<1,1><<<g, 128, gemmSmem>>>(h2h, h2l, w3h, w3l, K3 / GBK, BW_H2, K3, C3, b3, finp, out);
    }
    k_norm<<<BATCH * 32 / 256, 256>>>();

    // input Gram: 256x128 tiles, 2-term fp16  + hidden Gram: 3-term 128-tiles
    k_gram_big<<<272, 256, BG_SMEM>>>(eh, el, BW_E, BW_E / GBK, out + HOUT);
    k_gram_t<<<528, 128, gemmSmem>>>(fh, fl, KPAD_F, KPAD_F / GBK, out + HOUT + NPAIRS);
}

// round 10
// speedup vs baseline: 1.0990x; 1.0990x over previous
#include <cuda_runtime.h>
#include <cuda_fp16.h>
#include <cstdint>
#include <math.h>

// ---------------- problem constants ----------------
#define BATCH 4096
#define LSEQ  28
#define VOCAB 32000
#define DIM   300
#define BW_E  8704            // per-batch row: 300 front pad + 8400 data + 4 back pad
#define KPAD_F 128
#define K1    1504            // conv1/conv2 GEMM K (1500 padded)
#define K3    3008            // conv3 GEMM K (3000 padded)
#define BW_H1 3904            // 13*300 + 4
#define BW_H2 3008            // 5*600 + 8
#define L1o   13
#define C1    300
#define L2o   5
#define C2    600
#define C3    100
#define M1    (BATCH*L1o)     // 53248 = 416*128
#define M2    (BATCH*L2o)     // 20480 = 160*128
#define NPAIRS 8386560
#define HOUT  (BATCH*C3)

// ---------------- scratch ----------------
__device__ __half g_Eh[(size_t)BATCH*BW_E + 64];
__device__ __half g_El[(size_t)BATCH*BW_E + 64];
__device__ __half g_W1h[384*K1], g_W1l[384*K1];
__device__ __half g_W2h[640*K1], g_W2l[640*K1];
__device__ __half g_W3h[128*K3], g_W3l[128*K3];
__device__ float g_h1[(size_t)M1*C1];
__device__ float g_h2[(size_t)M2*C2];
__device__ __half g_h1h[(size_t)BATCH*BW_H1 + 64], g_h1l[(size_t)BATCH*BW_H1 + 64];
__device__ __half g_h2h[(size_t)BATCH*BW_H2 + 64], g_h2l[(size_t)BATCH*BW_H2 + 64];
__device__ float g_final[BATCH*C3];
__device__ __half g_Fnh[BATCH*KPAD_F], g_Fnl[BATCH*KPAD_F];
__device__ float g_scales[VOCAB];
__device__ float g_mean1[C1], g_istd1[C1];
__device__ float g_mean2[C2], g_istd2[C2];
__device__ float g_part[32*640*2];

// ---------------- embedding renorm scales ----------------
__global__ void k_scales(const float* __restrict__ emb) {
    int warp = (blockIdx.x * blockDim.x + threadIdx.x) >> 5;
    int lane = threadIdx.x & 31;
    if (warp >= VOCAB) return;
    const float* row = emb + (size_t)warp * DIM;
    float s = 0.f;
    for (int d = lane; d < DIM; d += 32) { float v = row[d]; s += v * v; }
    #pragma unroll
    for (int o = 16; o; o >>= 1) s += __shfl_xor_sync(0xffffffffu, s, o);
    if (lane == 0) g_scales[warp] = fminf(1.f, 1.f / (sqrtf(s) + 1e-7f));
}

// ---------------- gather into position-major E_T (+ fp16 split, + pads) ----------------
__global__ void k_gather(const int* __restrict__ x, const float* __restrict__ emb) {
    __shared__ int   tok[LSEQ];
    __shared__ float sc[LSEQ];
    int b = blockIdx.x, t = threadIdx.x;
    bool is64 = (x[1] == 0 && x[3] == 0 && x[5] == 0 && x[7] == 0);
    if (t < LSEQ) {
        int v = is64 ? x[(b * LSEQ + t) * 2] : x[b * LSEQ + t];
        tok[t] = v;
        sc[t]  = g_scales[v];
    }
    __syncthreads();
    __half* dH = g_Eh + (size_t)b * BW_E;
    __half* dL = g_El + (size_t)b * BW_E;
    const __half z = __float2half_rn(0.f);
    for (int i = t; i < 304; i += blockDim.x) {
        int o = (i < 300) ? i : (8400 + i);
        dH[o] = z; dL[o] = z;
    }
    for (int i = t; i < DIM * LSEQ; i += blockDim.x) {
        int l = i / DIM, ci = i - l * DIM;
        float v = emb[(size_t)tok[l] * DIM + ci] * sc[l];
        __half h = __float2half_rn(v);
        dH[300 + i] = h;
        dL[300 + i] = __float2half_rn(v - __half2float(h));
    }
}

// ---------------- weight prep ----------------
__global__ void k_prep_w(const float* __restrict__ w1, const float* __restrict__ w2,
                         const float* __restrict__ w3) {
    const int n1 = 384 * K1, n2 = 640 * K1, n3 = 128 * K3;
    int total = n1 + n2 + n3;
    for (int idx = blockIdx.x * blockDim.x + threadIdx.x; idx < total; idx += gridDim.x * blockDim.x) {
        int i = idx;
        if (i < n1) {
            int n = i / K1, k = i - n * K1;
            int kk = k / 300, ci = k - kk * 300;
            float v = (n < C1 && kk < 5) ? w1[n * 1500 + ci * 5 + kk] : 0.f;
            __half h = __float2half_rn(v);
            g_W1h[i] = h;
            g_W1l[i] = __float2half_rn(v - __half2float(h));
            continue;
        }
        i -= n1;
        if (i < n2) {
            int n = i / K1, k = i - n * K1;
            int kk = k / 300, ci = k - kk * 300;
            float v = (n < C2 && kk < 5) ? w2[n * 1500 + ci * 5 + kk] : 0.f;
            __half h = __float2half_rn(v);
            g_W2h[i] = h;
            g_W2l[i] = __float2half_rn(v - __half2float(h));
            continue;
        }
        i -= n2;
        {
            int n = i / K3, k = i - n * K3;
            int kk = k / 600, ci = k - kk * 600;
            float v = (n < C3 && kk < 5) ? w3[n * 3000 + ci * 5 + kk] : 0.f;
            __half h = __float2half_rn(v);
            g_W3h[i] = h;
            g_W3l[i] = __float2half_rn(v - __half2float(h));
        }
    }
}

// ---------------- zero tail pads ----------------
__global__ void k_padzero() {
    int b = blockIdx.x * blockDim.x + threadIdx.x;
    const __half z = __float2half_rn(0.f);
    if (b < BATCH) {
        #pragma unroll
        for (int i = 0; i < 4; i++) {
            g_h1h[(size_t)b * BW_H1 + 3900 + i] = z;
            g_h1l[(size_t)b * BW_H1 + 3900 + i] = z;
        }
        #pragma unroll
        for (int i = 0; i < 8; i++) {
            g_h2h[(size_t)b * BW_H2 + 3000 + i] = z;
            g_h2l[(size_t)b * BW_H2 + 3000 + i] = z;
        }
    }
    if (b < 64) {
        g_Eh[(size_t)BATCH * BW_E + b]  = z;
        g_El[(size_t)BATCH * BW_E + b]  = z;
        g_h1h[(size_t)BATCH * BW_H1 + b] = z;
        g_h1l[(size_t)BATCH * BW_H1 + b] = z;
        g_h2h[(size_t)BATCH * BW_H2 + b] = z;
        g_h2l[(size_t)BATCH * BW_H2 + b] = z;
    }
}

// ---------------- BN stats ----------------
__global__ void k_bnstat_p(const float* __restrict__ h, int M, int C) {
    int lane = threadIdx.x & 31;
    int w = threadIdx.x >> 5;
    int c = blockIdx.x * 32 + lane;
    int chunk = blockIdx.y;
    int rpc = M >> 5;
    float s = 0.f, s2 = 0.f;
    if (c < C) {
        int r1 = (chunk + 1) * rpc;
        for (int r = chunk * rpc + w; r < r1; r += 8) {
            float v = h[(size_t)r * C + c];
            s += v; s2 += v * v;
        }
    }
    __shared__ float sh[8][32][2];
    sh[w][lane][0] = s; sh[w][lane][1] = s2;
    __syncthreads();
    if (threadIdx.x < 32) {
        float S = 0.f, S2 = 0.f;
        #pragma unroll
        for (int i = 0; i < 8; i++) { S += sh[i][threadIdx.x][0]; S2 += sh[i][threadIdx.x][1]; }
        int cc = blockIdx.x * 32 + threadIdx.x;
        if (cc < C) {
            g_part[(chunk * 640 + cc) * 2 + 0] = S;
            g_part[(chunk * 640 + cc) * 2 + 1] = S2;
        }
    }
}

__global__ void k_bnstat_r(int C, float invN, float* __restrict__ mean, float* __restrict__ istd) {
    int c = blockIdx.x * blockDim.x + threadIdx.x;
    if (c >= C) return;
    float S = 0.f, S2 = 0.f;
    for (int ch = 0; ch < 32; ch++) {
        S  += g_part[(ch * 640 + c) * 2 + 0];
        S2 += g_part[(ch * 640 + c) * 2 + 1];
    }
    float m = S * invN;
    mean[c] = m;
    istd[c] = rsqrtf(S2 * invN - m * m + 1e-5f);
}

// ---------------- BN apply + ReLU + fp16 split into padded T layout ----------------
__global__ void k_bnapply(const float* __restrict__ h, __half* __restrict__ oh,
                          __half* __restrict__ ol,
                          const float* __restrict__ mean, const float* __restrict__ istd,
                          const float* __restrict__ gamma, const float* __restrict__ beta,
                          int M, int C, int lout, int pad) {
    size_t total = (size_t)M * C;
    size_t stride = (size_t)gridDim.x * blockDim.x;
    for (size_t idx = (size_t)blockIdx.x * blockDim.x + threadIdx.x; idx < total; idx += stride) {
        int m = (int)(idx / C), c = (int)(idx - (size_t)m * C);
        float v = (h[idx] - mean[c]) * istd[c] * gamma[c] + beta[c];
        v = fmaxf(v, 0.f);
        size_t off = idx + (size_t)pad * (m / lout);
        __half hi = __float2half_rn(v);
        oh[off] = hi;
        ol[off] = __float2half_rn(v - __half2float(hi));
    }
}

// ---------------- row-normalize final -> fp16 hi/lo ----------------
__global__ void k_norm() {
    int gw = (blockIdx.x * blockDim.x + threadIdx.x) >> 5;
    int lane = threadIdx.x & 31;
    if (gw >= BATCH) return;
    const float* f = g_final + gw * C3;
    float s = 0.f;
    for (int c = lane; c < C3; c += 32) { float v = f[c]; s += v * v; }
    #pragma unroll
    for (int o = 16; o; o >>= 1) s += __shfl_xor_sync(0xffffffffu, s, o);
    float n = sqrtf(s);
    __half* oh = g_Fnh + gw * KPAD_F;
    __half* ol = g_Fnl + gw * KPAD_F;
    for (int c = lane; c < C3; c += 32) {
        float v = f[c] / n;
        __half h = __float2half_rn(v);
        oh[c] = h;
        ol[c] = __float2half_rn(v - __half2float(h));
    }
    for (int c = C3 + lane; c < KPAD_F; c += 32) {
        oh[c] = __float2half_rn(0.f);
        ol[c] = __float2half_rn(0.f);
    }
}

// ================= HMMA GEMM machinery (split-fp16, swizzled smem) =================
// CTA 128x128, 128 threads = 4 warps of 64x64. 3-stage cp.async pipeline, Kc=32.
// THREE=true : C = Ah*Bh + Ah*Bl + Al*Bh  (err ~2^-22)
// THREE=false: C = Ah*Bh + Ah*Bl          (err ~2^-12, A-lo never loaded)
#define GBM 128
#define GBK 32
#define GSTAGES 3
#define MSZ (128*32)
#define STG (4*MSZ)

__device__ __forceinline__ void cp16(__half* dst, const __half* src) {
    unsigned a = (unsigned)__cvta_generic_to_shared(dst);
    asm volatile("cp.async.cg.shared.global [%0], [%1], 16;\n" :: "r"(a), "l"(src));
}
__device__ __forceinline__ void ldm4(unsigned* r, const __half* p) {
    unsigned a = (unsigned)__cvta_generic_to_shared(p);
    asm volatile("ldmatrix.sync.aligned.m8n8.x4.shared.b16 {%0,%1,%2,%3}, [%4];\n"
                 : "=r"(r[0]), "=r"(r[1]), "=r"(r[2]), "=r"(r[3]) : "r"(a));
}
__device__ __forceinline__ void mma16816(float* d, const unsigned* a, const unsigned* b) {
    asm volatile("mma.sync.aligned.m16n8k16.row.col.f32.f16.f16.f32 "
                 "{%0,%1,%2,%3}, {%4,%5,%6,%7}, {%8,%9}, {%0,%1,%2,%3};\n"
                 : "+f"(d[0]), "+f"(d[1]), "+f"(d[2]), "+f"(d[3])
                 : "r"(a[0]), "r"(a[1]), "r"(a[2]), "r"(a[3]), "r"(b[0]), "r"(b[1]));
}
__device__ __forceinline__ int swz(int row, int chunk) {
    return row * 32 + ((chunk ^ ((row >> 1) & 3)) << 3);
}

// A rows: ptr = Ah + (row/LA)*bwA + (row%LA)*600 + k
template<int LA, bool THREE>
__device__ __forceinline__ void load_stage(__half* dst,
        const __half* Ah, const __half* Al,
        const __half* Bh, const __half* Bl,
        int i0, int j0, int kc, int bwA, int bwB, int t) {
    #pragma unroll
    for (int q = 0; q < 4; q++) {
        int idx = t + q * 128;
        int row = idx >> 2, c = idx & 3;
        int so = swz(row, c);
        int ra = i0 + row;
        int ba = ra / LA, la = ra - ba * LA;
        size_t goA = (size_t)ba * bwA + la * 600 + kc + c * 8;
        size_t goB = (size_t)(j0 + row) * bwB + kc + c * 8;
        cp16(dst + 0 * MSZ + so, Ah + goA);
        if (THREE) cp16(dst + 1 * MSZ + so, Al + goA);
        cp16(dst + 2 * MSZ + so, Bh + goB);
        cp16(dst + 3 * MSZ + so, Bl + goB);
    }
}

template<int LA, bool THREE>
__device__ __forceinline__ void gemm_core(
        const __half* Ah, const __half* Al,
        const __half* Bh, const __half* Bl,
        int i0, int j0, int bwA, int bwB, int kIters,
        __half* sm, int t, float acc[4][8][4]) {
    int lane = t & 31, wid = t >> 5;
    int wm = wid & 1, wn = wid >> 1;      // 2x2 warp grid, 64x64 per warp
    int lr = lane & 15, lc = (lane >> 4) << 3;

    #pragma unroll
    for (int s = 0; s < GSTAGES - 1; s++) {
        if (s < kIters) load_stage<LA, THREE>(sm + s * STG, Ah, Al, Bh, Bl, i0, j0, s * GBK, bwA, bwB, t);
        asm volatile("cp.async.commit_group;\n");
    }
    for (int it = 0; it < kIters; it++) {
        asm volatile("cp.async.wait_group %0;\n" :: "n"(GSTAGES - 2));
        __syncthreads();
        int nxt = it + GSTAGES - 1;
        if (nxt < kIters) load_stage<LA, THREE>(sm + (nxt % GSTAGES) * STG, Ah, Al, Bh, Bl, i0, j0, nxt * GBK, bwA, bwB, t);
        asm volatile("cp.async.commit_group;\n");

        const __half* buf = sm + (it % GSTAGES) * STG;
        const __half* sAh = buf;
        const __half* sAl = buf + MSZ;
        const __half* sBh = buf + 2 * MSZ;
        const __half* sBl = buf + 3 * MSZ;

        #pragma unroll
        for (int ks = 0; ks < GBK; ks += 16) {
            unsigned ah[4][4], al[4][4], bh[8][2], bl[8][2];
            int cl = (ks + lc) >> 3;
            #pragma unroll
            for (int mt = 0; mt < 4; mt++) {
                int rA = wm * 64 + mt * 16 + lr;
                ldm4(ah[mt], sAh + swz(rA, cl));
                if (THREE) ldm4(al[mt], sAl + swz(rA, cl));
            }
            #pragma unroll
            for (int bt = 0; bt < 4; bt++) {
                int rB = wn * 64 + bt * 16 + lr;
                unsigned r4[4];
                ldm4(r4, sBh + swz(rB, cl));
                bh[2 * bt][0] = r4[0]; bh[2 * bt][1] = r4[2];
                bh[2 * bt + 1][0] = r4[1]; bh[2 * bt + 1][1] = r4[3];
                ldm4(r4, sBl + swz(rB, cl));
                bl[2 * bt][0] = r4[0]; bl[2 * bt][1] = r4[2];
                bl[2 * bt + 1][0] = r4[1]; bl[2 * bt + 1][1] = r4[3];
            }
            #pragma unroll
            for (int mt = 0; mt < 4; mt++)
                #pragma unroll
                for (int nt = 0; nt < 8; nt++) {
                    mma16816(acc[mt][nt], ah[mt], bh[nt]);
                    mma16816(acc[mt][nt], ah[mt], bl[nt]);
                    if (THREE) mma16816(acc[mt][nt], al[mt], bh[nt]);
                }
        }
        __syncthreads();
    }
}

// ---------------- symmetric Gram, triu-packed output ----------------
template<bool THREE>
__global__ __launch_bounds__(128, 2)
void k_gram_t(const __half* __restrict__ Xhi, const __half* __restrict__ Xlo,
              int ldk, int kIters, float* __restrict__ out) {
    extern __shared__ __half sm[];
    int p = blockIdx.x;
    int ti = 0, rem = 32;
    while (p >= rem) { p -= rem; rem--; ti++; }
    int tj = ti + p;
    const int i0 = ti * GBM, j0 = tj * GBM;

    int t = threadIdx.x;
    float acc[4][8][4];
    #pragma unroll
    for (int mt = 0; mt < 4; mt++)
        #pragma unroll
        for (int nt = 0; nt < 8; nt++)
            #pragma unroll
            for (int e = 0; e < 4; e++) acc[mt][nt][e] = 0.f;

    gemm_core<1, THREE>(Xhi, Xlo, Xhi, Xlo, i0, j0, ldk, ldk, kIters, sm, t, acc);

    int lane = t & 31, wid = t >> 5;
    int wm = wid & 1, wn = wid >> 1;
    int r = lane >> 2, cp = (lane & 3) * 2;
    #pragma unroll
    for (int mt = 0; mt < 4; mt++) {
        #pragma unroll
        for (int h = 0; h < 2; h++) {
            int i = i0 + wm * 64 + mt * 16 + r + h * 8;
            int base = i * (8191 - i) / 2 - i - 1;
            #pragma unroll
            for (int nt = 0; nt < 8; nt++) {
                int j = j0 + wn * 64 + nt * 8 + cp;
                if (j > i)     out[base + j]     = acc[mt][nt][2 * h + 0];
                if (j + 1 > i) out[base + j + 1] = acc[mt][nt][2 * h + 1];
            }
        }
    }
}

// ---------------- conv GEMM: implicit im2col; MODE 0: bias; MODE 1: bias+tanh -> dst & out2 ----------------
template<int LA, int MODE>
__global__ __launch_bounds__(128, 2)
void k_conv_gemm(const __half* __restrict__ Ah, const __half* __restrict__ Al,
                 const __half* __restrict__ Bh, const __half* __restrict__ Bl,
                 int kIters, int bwA, int bwB, int Cout,
                 const float* __restrict__ bias, float* __restrict__ dst, float* __restrict__ out2) {
    extern __shared__ __half sm[];
    const int n0 = blockIdx.x * GBM, m0 = blockIdx.y * GBM;

    int t = threadIdx.x;
    float acc[4][8][4];
    #pragma unroll
    for (int mt = 0; mt < 4; mt++)
        #pragma unroll
        for (int nt = 0; nt < 8; nt++)
            #pragma unroll
            for (int e = 0; e < 4; e++) acc[mt][nt][e] = 0.f;

    gemm_core<LA, true>(Ah, Al, Bh, Bl, m0, n0, bwA, bwB, kIters, sm, t, acc);

    int lane = t & 31, wid = t >> 5;
    int wm = wid & 1, wn = wid >> 1;
    int r = lane >> 2, cp = (lane & 3) * 2;
    #pragma unroll
    for (int mt = 0; mt < 4; mt++) {
        #pragma unroll
        for (int h = 0; h < 2; h++) {
            int m = m0 + wm * 64 + mt * 16 + r + h * 8;
            #pragma unroll
            for (int nt = 0; nt < 8; nt++) {
                int n = n0 + wn * 64 + nt * 8 + cp;
                float a0 = acc[mt][nt][2 * h + 0];
                float a1 = acc[mt][nt][2 * h + 1];
                if (MODE == 0) {
                    if (n < Cout)     dst[(size_t)m * Cout + n]     = a0 + bias[n];
                    if (n + 1 < Cout) dst[(size_t)m * Cout + n + 1] = a1 + bias[n + 1];
                } else {
                    if (n < Cout) {
                        float v = tanhf(a0 + bias[n]);
                        dst[(size_t)m * Cout + n] = v;
                        out2[(size_t)m * Cout + n] = v;
                    }
                    if (n + 1 < Cout) {
                        float v = tanhf(a1 + bias[n + 1]);
                        dst[(size_t)m * Cout + n + 1] = v;
                        out2[(size_t)m * Cout + n + 1] = v;
                    }
                }
            }
        }
    }
}

// ---------------- launch ----------------
extern "C" void kernel_launch(void* const* d_in, const int* in_sizes, int n_in,
                              void* d_out, int out_size) {
    const int*   x   = (const int*)  d_in[0];
    const float* emb = (const float*)d_in[1];
    const float* w1  = (const float*)d_in[2];
    const float* b1  = (const float*)d_in[3];
    const float* w2  = (const float*)d_in[4];
    const float* b2  = (const float*)d_in[5];
    const float* w3  = (const float*)d_in[6];
    const float* b3  = (const float*)d_in[7];
    const float* g1  = (const float*)d_in[8];
    const float* be1 = (const float*)d_in[9];
    const float* g2  = (const float*)d_in[10];
    const float* be2 = (const float*)d_in[11];
    float* out = (float*)d_out;

    const int gemmSmem = GSTAGES * STG * 2;   // 98304 bytes
    cudaFuncSetAttribute(k_gram_t<false>,   cudaFuncAttributeMaxDynamicSharedMemorySize, gemmSmem);
    cudaFuncSetAttribute(k_gram_t<true>,    cudaFuncAttributeMaxDynamicSharedMemorySize, gemmSmem);
    cudaFuncSetAttribute(k_conv_gemm<13,0>, cudaFuncAttributeMaxDynamicSharedMemorySize, gemmSmem);
    cudaFuncSetAttribute(k_conv_gemm<5,0>,  cudaFuncAttributeMaxDynamicSharedMemorySize, gemmSmem);
    cudaFuncSetAttribute(k_conv_gemm<1,1>,  cudaFuncAttributeMaxDynamicSharedMemorySize, gemmSmem);

    __half *eh, *el, *w1h, *w1l, *w2h, *w2l, *w3h, *w3l;
    __half *h1h, *h1l, *h2h, *h2l, *fh, *fl;
    float *h1p, *h2p, *finp, *m1p, *i1p, *m2p, *i2p;
    cudaGetSymbolAddress((void**)&eh,  g_Eh);
    cudaGetSymbolAddress((void**)&el,  g_El);
    cudaGetSymbolAddress((void**)&w1h, g_W1h);
    cudaGetSymbolAddress((void**)&w1l, g_W1l);
    cudaGetSymbolAddress((void**)&w2h, g_W2h);
    cudaGetSymbolAddress((void**)&w2l, g_W2l);
    cudaGetSymbolAddress((void**)&w3h, g_W3h);
    cudaGetSymbolAddress((void**)&w3l, g_W3l);
    cudaGetSymbolAddress((void**)&h1h, g_h1h);
    cudaGetSymbolAddress((void**)&h1l, g_h1l);
    cudaGetSymbolAddress((void**)&h2h, g_h2h);
    cudaGetSymbolAddress((void**)&h2l, g_h2l);
    cudaGetSymbolAddress((void**)&fh,  g_Fnh);
    cudaGetSymbolAddress((void**)&fl,  g_Fnl);
    cudaGetSymbolAddress((void**)&h1p, g_h1);
    cudaGetSymbolAddress((void**)&h2p, g_h2);
    cudaGetSymbolAddress((void**)&finp, g_final);
    cudaGetSymbolAddress((void**)&m1p, g_mean1);
    cudaGetSymbolAddress((void**)&i1p, g_istd1);
    cudaGetSymbolAddress((void**)&m2p, g_mean2);
    cudaGetSymbolAddress((void**)&i2p, g_istd2);

    // ---- prologue on the main (capture) stream ----
    k_scales<<<(VOCAB * 32 + 255) / 256, 256>>>(emb);
    k_gather<<<BATCH, 256>>>(x, emb);
    k_prep_w<<<1024, 256>>>(w1, w2, w3);
    k_padzero<<<16, 256>>>();

    // ---- fork: big input Gram runs concurrently with the conv chain ----
    cudaStream_t s2;
    cudaStreamCreateWithFlags(&s2, cudaStreamNonBlocking);
    cudaEvent_t evFork, evJoin;
    cudaEventCreateWithFlags(&evFork, cudaEventDisableTiming);
    cudaEventCreateWithFlags(&evJoin, cudaEventDisableTiming);

    cudaEventRecord(evFork, 0);
    cudaStreamWaitEvent(s2, evFork, 0);

    // input Gram: fp16 2-term (A-lo dropped) on side stream
    k_gram_t<false><<<528, 128, gemmSmem, s2>>>(eh, el, BW_E, BW_E / GBK, out + HOUT);
    cudaEventRecord(evJoin, s2);

    // ---- conv chain on the main stream ----
    {
        dim3 g(3, M1 / GBM);
        k_conv_gemm<13,0><<<g, 128, gemmSmem>>>(eh, el, w1h, w1l, (K1 + GBK - 1) / GBK, BW_E, K1, C1, b1, h1p, nullptr);
    }
    k_bnstat_p<<<dim3(10, 32), 256>>>(h1p, M1, C1);
    k_bnstat_r<<<2, 256>>>(C1, 1.f / M1, m1p, i1p);
    k_bnapply<<<2048, 256>>>(h1p, h1h, h1l, m1p, i1p, g1, be1, M1, C1, L1o, 4);

    {
        dim3 g(5, M2 / GBM);
        k_conv_gemm<5,0><<<g, 128, gemmSmem>>>(h1h, h1l, w2h, w2l, (K1 + GBK - 1) / GBK, BW_H1, K1, C2, b2, h2p, nullptr);
    }
    k_bnstat_p<<<dim3(19, 32), 256>>>(h2p, M2, C2);
    k_bnstat_r<<<3, 256>>>(C2, 1.f / M2, m2p, i2p);
    k_bnapply<<<2048, 256>>>(h2p, h2h, h2l, m2p, i2p, g2, be2, M2, C2, L2o, 8);

    {
        dim3 g(1, BATCH / GBM);
        k_conv_gemm<1,1><<<g, 128, gemmSmem>>>(h2h, h2l, w3h, w3l, K3 / GBK, BW_H2, K3, C3, b3, finp, out);
    }
    k_norm<<<BATCH * 32 / 256, 256>>>();

    // hidden Gram: 3-term 128-tiles on main stream
    k_gram_t<true><<<528, 128, gemmSmem>>>(fh, fl, KPAD_F, KPAD_F / GBK, out + HOUT + NPAIRS);

    // ---- join side stream back into the main stream ----
    cudaStreamWaitEvent(0, evJoin, 0);

    cudaEventDestroy(evFork);
    cudaEventDestroy(evJoin);
    cudaStreamDestroy(s2);
}

// round 11
// speedup vs baseline: 1.2956x; 1.1789x over previous
#include <cuda_runtime.h>
#include <cuda_fp16.h>
#include <cstdint>
#include <math.h>

// ---------------- problem constants ----------------
#define BATCH 4096
#define LSEQ  28
#define VOCAB 32000
#define DIM   300
#define BW_E  8704            // per-batch row: 300 front pad + 8400 data + 4 back pad
#define KPAD_F 128
#define K1    1504            // conv1/conv2 GEMM K (1500 padded)
#define K3    3008            // conv3 GEMM K (3000 padded)
#define BW_H1 3904            // 13*300 + 4
#define BW_H2 3008            // 5*600 + 8
#define L1o   13
#define C1    300
#define L2o   5
#define C2    600
#define C3    100
#define M1    (BATCH*L1o)     // 53248 = 416*128
#define M2    (BATCH*L2o)     // 20480 = 160*128
#define NPAIRS 8386560
#define HOUT  (BATCH*C3)

// ---------------- scratch ----------------
__device__ __half g_Eh[(size_t)BATCH*BW_E + 64];
__device__ __half g_El[(size_t)BATCH*BW_E + 64];
__device__ __half g_W1h[384*K1], g_W1l[384*K1];
__device__ __half g_W2h[640*K1], g_W2l[640*K1];
__device__ __half g_W3h[128*K3], g_W3l[128*K3];
__device__ float g_h1[(size_t)M1*C1];
__device__ float g_h2[(size_t)M2*C2];
__device__ __half g_h1h[(size_t)BATCH*BW_H1 + 64], g_h1l[(size_t)BATCH*BW_H1 + 64];
__device__ __half g_h2h[(size_t)BATCH*BW_H2 + 64], g_h2l[(size_t)BATCH*BW_H2 + 64];
__device__ float g_final[BATCH*C3];
__device__ __half g_Fnh[BATCH*KPAD_F], g_Fnl[BATCH*KPAD_F];
__device__ float g_scales[VOCAB];
__device__ float g_mean1[C1], g_istd1[C1];
__device__ float g_mean2[C2], g_istd2[C2];
__device__ float g_part[32*640*2];

// ---------------- embedding renorm scales ----------------
__global__ void k_scales(const float* __restrict__ emb) {
    int warp = (blockIdx.x * blockDim.x + threadIdx.x) >> 5;
    int lane = threadIdx.x & 31;
    if (warp >= VOCAB) return;
    const float* row = emb + (size_t)warp * DIM;
    float s = 0.f;
    for (int d = lane; d < DIM; d += 32) { float v = row[d]; s += v * v; }
    #pragma unroll
    for (int o = 16; o; o >>= 1) s += __shfl_xor_sync(0xffffffffu, s, o);
    if (lane == 0) g_scales[warp] = fminf(1.f, 1.f / (sqrtf(s) + 1e-7f));
}

// ---------------- gather into position-major E_T (+ fp16 split, + pads) ----------------
__global__ void k_gather(const int* __restrict__ x, const float* __restrict__ emb) {
    __shared__ int   tok[LSEQ];
    __shared__ float sc[LSEQ];
    int b = blockIdx.x, t = threadIdx.x;
    bool is64 = (x[1] == 0 && x[3] == 0 && x[5] == 0 && x[7] == 0);
    if (t < LSEQ) {
        int v = is64 ? x[(b * LSEQ + t) * 2] : x[b * LSEQ + t];
        tok[t] = v;
        sc[t]  = g_scales[v];
    }
    __syncthreads();
    __half* dH = g_Eh + (size_t)b * BW_E;
    __half* dL = g_El + (size_t)b * BW_E;
    const __half z = __float2half_rn(0.f);
    for (int i = t; i < 304; i += blockDim.x) {
        int o = (i < 300) ? i : (8400 + i);
        dH[o] = z; dL[o] = z;
    }
    for (int i = t; i < DIM * LSEQ; i += blockDim.x) {
        int l = i / DIM, ci = i - l * DIM;
        float v = emb[(size_t)tok[l] * DIM + ci] * sc[l];
        __half h = __float2half_rn(v);
        dH[300 + i] = h;
        dL[300 + i] = __float2half_rn(v - __half2float(h));
    }
}

// ---------------- weight prep ----------------
__global__ void k_prep_w(const float* __restrict__ w1, const float* __restrict__ w2,
                         const float* __restrict__ w3) {
    const int n1 = 384 * K1, n2 = 640 * K1, n3 = 128 * K3;
    int total = n1 + n2 + n3;
    for (int idx = blockIdx.x * blockDim.x + threadIdx.x; idx < total; idx += gridDim.x * blockDim.x) {
        int i = idx;
        if (i < n1) {
            int n = i / K1, k = i - n * K1;
            int kk = k / 300, ci = k - kk * 300;
            float v = (n < C1 && kk < 5) ? w1[n * 1500 + ci * 5 + kk] : 0.f;
            __half h = __float2half_rn(v);
            g_W1h[i] = h;
            g_W1l[i] = __float2half_rn(v - __half2float(h));
            continue;
        }
        i -= n1;
        if (i < n2) {
            int n = i / K1, k = i - n * K1;
            int kk = k / 300, ci = k - kk * 300;
            float v = (n < C2 && kk < 5) ? w2[n * 1500 + ci * 5 + kk] : 0.f;
            __half h = __float2half_rn(v);
            g_W2h[i] = h;
            g_W2l[i] = __float2half_rn(v - __half2float(h));
            continue;
        }
        i -= n2;
        {
            int n = i / K3, k = i - n * K3;
            int kk = k / 600, ci = k - kk * 600;
            float v = (n < C3 && kk < 5) ? w3[n * 3000 + ci * 5 + kk] : 0.f;
            __half h = __float2half_rn(v);
            g_W3h[i] = h;
            g_W3l[i] = __float2half_rn(v - __half2float(h));
        }
    }
}

// ---------------- zero tail pads ----------------
__global__ void k_padzero() {
    int b = blockIdx.x * blockDim.x + threadIdx.x;
    const __half z = __float2half_rn(0.f);
    if (b < BATCH) {
        #pragma unroll
        for (int i = 0; i < 4; i++) {
            g_h1h[(size_t)b * BW_H1 + 3900 + i] = z;
            g_h1l[(size_t)b * BW_H1 + 3900 + i] = z;
        }
        #pragma unroll
        for (int i = 0; i < 8; i++) {
            g_h2h[(size_t)b * BW_H2 + 3000 + i] = z;
            g_h2l[(size_t)b * BW_H2 + 3000 + i] = z;
        }
    }
    if (b < 64) {
        g_Eh[(size_t)BATCH * BW_E + b]  = z;
        g_El[(size_t)BATCH * BW_E + b]  = z;
        g_h1h[(size_t)BATCH * BW_H1 + b] = z;
        g_h1l[(size_t)BATCH * BW_H1 + b] = z;
        g_h2h[(size_t)BATCH * BW_H2 + b] = z;
        g_h2l[(size_t)BATCH * BW_H2 + b] = z;
    }
}

// ---------------- BN stats ----------------
__global__ void k_bnstat_p(const float* __restrict__ h, int M, int C) {
    int lane = threadIdx.x & 31;
    int w = threadIdx.x >> 5;
    int c = blockIdx.x * 32 + lane;
    int chunk = blockIdx.y;
    int rpc = M >> 5;
    float s = 0.f, s2 = 0.f;
    if (c < C) {
        int r1 = (chunk + 1) * rpc;
        for (int r = chunk * rpc + w; r < r1; r += 8) {
            float v = h[(size_t)r * C + c];
            s += v; s2 += v * v;
        }
    }
    __shared__ float sh[8][32][2];
    sh[w][lane][0] = s; sh[w][lane][1] = s2;
    __syncthreads();
    if (threadIdx.x < 32) {
        float S = 0.f, S2 = 0.f;
        #pragma unroll
        for (int i = 0; i < 8; i++) { S += sh[i][threadIdx.x][0]; S2 += sh[i][threadIdx.x][1]; }
        int cc = blockIdx.x * 32 + threadIdx.x;
        if (cc < C) {
            g_part[(chunk * 640 + cc) * 2 + 0] = S;
            g_part[(chunk * 640 + cc) * 2 + 1] = S2;
        }
    }
}

__global__ void k_bnstat_r(int C, float invN, float* __restrict__ mean, float* __restrict__ istd) {
    int c = blockIdx.x * blockDim.x + threadIdx.x;
    if (c >= C) return;
    float S = 0.f, S2 = 0.f;
    for (int ch = 0; ch < 32; ch++) {
        S  += g_part[(ch * 640 + c) * 2 + 0];
        S2 += g_part[(ch * 640 + c) * 2 + 1];
    }
    float m = S * invN;
    mean[c] = m;
    istd[c] = rsqrtf(S2 * invN - m * m + 1e-5f);
}

// ---------------- BN apply + ReLU + fp16 split into padded T layout ----------------
__global__ void k_bnapply(const float* __restrict__ h, __half* __restrict__ oh,
                          __half* __restrict__ ol,
                          const float* __restrict__ mean, const float* __restrict__ istd,
                          const float* __restrict__ gamma, const float* __restrict__ beta,
                          int M, int C, int lout, int pad) {
    size_t total = (size_t)M * C;
    size_t stride = (size_t)gridDim.x * blockDim.x;
    for (size_t idx = (size_t)blockIdx.x * blockDim.x + threadIdx.x; idx < total; idx += stride) {
        int m = (int)(idx / C), c = (int)(idx - (size_t)m * C);
        float v = (h[idx] - mean[c]) * istd[c] * gamma[c] + beta[c];
        v = fmaxf(v, 0.f);
        size_t off = idx + (size_t)pad * (m / lout);
        __half hi = __float2half_rn(v);
        oh[off] = hi;
        ol[off] = __float2half_rn(v - __half2float(hi));
    }
}

// ---------------- row-normalize final -> fp16 hi/lo ----------------
__global__ void k_norm() {
    int gw = (blockIdx.x * blockDim.x + threadIdx.x) >> 5;
    int lane = threadIdx.x & 31;
    if (gw >= BATCH) return;
    const float* f = g_final + gw * C3;
    float s = 0.f;
    for (int c = lane; c < C3; c += 32) { float v = f[c]; s += v * v; }
    #pragma unroll
    for (int o = 16; o; o >>= 1) s += __shfl_xor_sync(0xffffffffu, s, o);
    float n = sqrtf(s);
    __half* oh = g_Fnh + gw * KPAD_F;
    __half* ol = g_Fnl + gw * KPAD_F;
    for (int c = lane; c < C3; c += 32) {
        float v = f[c] / n;
        __half h = __float2half_rn(v);
        oh[c] = h;
        ol[c] = __float2half_rn(v - __half2float(h));
    }
    for (int c = C3 + lane; c < KPAD_F; c += 32) {
        oh[c] = __float2half_rn(0.f);
        ol[c] = __float2half_rn(0.f);
    }
}

// ================= HMMA GEMM machinery (split-fp16, swizzled smem) =================
// CTA 128x128, 128 threads = 4 warps of 64x64. 3-stage cp.async pipeline, Kc=32.
// THREE=true : C = Ah*Bh + Ah*Bl + Al*Bh  (err ~2^-22)
// THREE=false: C = Ah*Bh + Ah*Bl          (err ~2^-12, A-lo never loaded)
#define GBM 128
#define GBK 32
#define GSTAGES 3
#define MSZ (128*32)
#define STG (4*MSZ)

__device__ __forceinline__ void cp16(__half* dst, const __half* src) {
    unsigned a = (unsigned)__cvta_generic_to_shared(dst);
    asm volatile("cp.async.cg.shared.global [%0], [%1], 16;\n" :: "r"(a), "l"(src));
}
__device__ __forceinline__ void ldm4(unsigned* r, const __half* p) {
    unsigned a = (unsigned)__cvta_generic_to_shared(p);
    asm volatile("ldmatrix.sync.aligned.m8n8.x4.shared.b16 {%0,%1,%2,%3}, [%4];\n"
                 : "=r"(r[0]), "=r"(r[1]), "=r"(r[2]), "=r"(r[3]) : "r"(a));
}
__device__ __forceinline__ void mma16816(float* d, const unsigned* a, const unsigned* b) {
    asm volatile("mma.sync.aligned.m16n8k16.row.col.f32.f16.f16.f32 "
                 "{%0,%1,%2,%3}, {%4,%5,%6,%7}, {%8,%9}, {%0,%1,%2,%3};\n"
                 : "+f"(d[0]), "+f"(d[1]), "+f"(d[2]), "+f"(d[3])
                 : "r"(a[0]), "r"(a[1]), "r"(a[2]), "r"(a[3]), "r"(b[0]), "r"(b[1]));
}
__device__ __forceinline__ int swz(int row, int chunk) {
    return row * 32 + ((chunk ^ ((row >> 1) & 3)) << 3);
}

// A rows: ptr = Ah + (row/LA)*bwA + (row%LA)*600 + k
template<int LA, bool THREE>
__device__ __forceinline__ void load_stage(__half* dst,
        const __half* Ah, const __half* Al,
        const __half* Bh, const __half* Bl,
        int i0, int j0, int kc, int bwA, int bwB, int t) {
    #pragma unroll
    for (int q = 0; q < 4; q++) {
        int idx = t + q * 128;
        int row = idx >> 2, c = idx & 3;
        int so = swz(row, c);
        int ra = i0 + row;
        int ba = ra / LA, la = ra - ba * LA;
        size_t goA = (size_t)ba * bwA + la * 600 + kc + c * 8;
        size_t goB = (size_t)(j0 + row) * bwB + kc + c * 8;
        cp16(dst + 0 * MSZ + so, Ah + goA);
        if (THREE) cp16(dst + 1 * MSZ + so, Al + goA);
        cp16(dst + 2 * MSZ + so, Bh + goB);
        cp16(dst + 3 * MSZ + so, Bl + goB);
    }
}

template<int LA, bool THREE>
__device__ __forceinline__ void gemm_core(
        const __half* Ah, const __half* Al,
        const __half* Bh, const __half* Bl,
        int i0, int j0, int bwA, int bwB, int kIters,
        __half* sm, int t, float acc[4][8][4]) {
    int lane = t & 31, wid = t >> 5;
    int wm = wid & 1, wn = wid >> 1;      // 2x2 warp grid, 64x64 per warp
    int lr = lane & 15, lc = (lane >> 4) << 3;

    #pragma unroll
    for (int s = 0; s < GSTAGES - 1; s++) {
        if (s < kIters) load_stage<LA, THREE>(sm + s * STG, Ah, Al, Bh, Bl, i0, j0, s * GBK, bwA, bwB, t);
        asm volatile("cp.async.commit_group;\n");
    }
    for (int it = 0; it < kIters; it++) {
        asm volatile("cp.async.wait_group %0;\n" :: "n"(GSTAGES - 2));
        __syncthreads();
        int nxt = it + GSTAGES - 1;
        if (nxt < kIters) load_stage<LA, THREE>(sm + (nxt % GSTAGES) * STG, Ah, Al, Bh, Bl, i0, j0, nxt * GBK, bwA, bwB, t);
        asm volatile("cp.async.commit_group;\n");

        const __half* buf = sm + (it % GSTAGES) * STG;
        const __half* sAh = buf;
        const __half* sAl = buf + MSZ;
        const __half* sBh = buf + 2 * MSZ;
        const __half* sBl = buf + 3 * MSZ;

        #pragma unroll
        for (int ks = 0; ks < GBK; ks += 16) {
            unsigned ah[4][4], al[4][4], bh[8][2], bl[8][2];
            int cl = (ks + lc) >> 3;
            #pragma unroll
            for (int mt = 0; mt < 4; mt++) {
                int rA = wm * 64 + mt * 16 + lr;
                ldm4(ah[mt], sAh + swz(rA, cl));
                if (THREE) ldm4(al[mt], sAl + swz(rA, cl));
            }
            #pragma unroll
            for (int bt = 0; bt < 4; bt++) {
                int rB = wn * 64 + bt * 16 + lr;
                unsigned r4[4];
                ldm4(r4, sBh + swz(rB, cl));
                bh[2 * bt][0] = r4[0]; bh[2 * bt][1] = r4[2];
                bh[2 * bt + 1][0] = r4[1]; bh[2 * bt + 1][1] = r4[3];
                ldm4(r4, sBl + swz(rB, cl));
                bl[2 * bt][0] = r4[0]; bl[2 * bt][1] = r4[2];
                bl[2 * bt + 1][0] = r4[1]; bl[2 * bt + 1][1] = r4[3];
            }
            #pragma unroll
            for (int mt = 0; mt < 4; mt++)
                #pragma unroll
                for (int nt = 0; nt < 8; nt++) {
                    mma16816(acc[mt][nt], ah[mt], bh[nt]);
                    mma16816(acc[mt][nt], ah[mt], bl[nt]);
                    if (THREE) mma16816(acc[mt][nt], al[mt], bh[nt]);
                }
        }
        __syncthreads();
    }
}

// ---------------- symmetric Gram, triu-packed output ----------------
template<bool THREE>
__global__ __launch_bounds__(128, 2)
void k_gram_t(const __half* __restrict__ Xhi, const __half* __restrict__ Xlo,
              int ldk, int kIters, float* __restrict__ out) {
    extern __shared__ __half sm[];
    int p = blockIdx.x;
    int ti = 0, rem = 32;
    while (p >= rem) { p -= rem; rem--; ti++; }
    int tj = ti + p;
    const int i0 = ti * GBM, j0 = tj * GBM;

    int t = threadIdx.x;
    float acc[4][8][4];
    #pragma unroll
    for (int mt = 0; mt < 4; mt++)
        #pragma unroll
        for (int nt = 0; nt < 8; nt++)
            #pragma unroll
            for (int e = 0; e < 4; e++) acc[mt][nt][e] = 0.f;

    gemm_core<1, THREE>(Xhi, Xlo, Xhi, Xlo, i0, j0, ldk, ldk, kIters, sm, t, acc);

    int lane = t & 31, wid = t >> 5;
    int wm = wid & 1, wn = wid >> 1;
    int r = lane >> 2, cp = (lane & 3) * 2;
    #pragma unroll
    for (int mt = 0; mt < 4; mt++) {
        #pragma unroll
        for (int h = 0; h < 2; h++) {
            int i = i0 + wm * 64 + mt * 16 + r + h * 8;
            int base = i * (8191 - i) / 2 - i - 1;
            #pragma unroll
            for (int nt = 0; nt < 8; nt++) {
                int j = j0 + wn * 64 + nt * 8 + cp;
                if (j > i)     out[base + j]     = acc[mt][nt][2 * h + 0];
                if (j + 1 > i) out[base + j + 1] = acc[mt][nt][2 * h + 1];
            }
        }
    }
}

// ---------------- conv GEMM: implicit im2col; MODE 0: bias; MODE 1: bias+tanh -> dst & out2 ----------------
template<int LA, int MODE, bool THREE>
__global__ __launch_bounds__(128, 2)
void k_conv_gemm(const __half* __restrict__ Ah, const __half* __restrict__ Al,
                 const __half* __restrict__ Bh, const __half* __restrict__ Bl,
                 int kIters, int bwA, int bwB, int Cout,
                 const float* __restrict__ bias, float* __restrict__ dst, float* __restrict__ out2) {
    extern __shared__ __half sm[];
    const int n0 = blockIdx.x * GBM, m0 = blockIdx.y * GBM;

    int t = threadIdx.x;
    float acc[4][8][4];
    #pragma unroll
    for (int mt = 0; mt < 4; mt++)
        #pragma unroll
        for (int nt = 0; nt < 8; nt++)
            #pragma unroll
            for (int e = 0; e < 4; e++) acc[mt][nt][e] = 0.f;

    gemm_core<LA, THREE>(Ah, Al, Bh, Bl, m0, n0, bwA, bwB, kIters, sm, t, acc);

    int lane = t & 31, wid = t >> 5;
    int wm = wid & 1, wn = wid >> 1;
    int r = lane >> 2, cp = (lane & 3) * 2;
    #pragma unroll
    for (int mt = 0; mt < 4; mt++) {
        #pragma unroll
        for (int h = 0; h < 2; h++) {
            int m = m0 + wm * 64 + mt * 16 + r + h * 8;
            #pragma unroll
            for (int nt = 0; nt < 8; nt++) {
                int n = n0 + wn * 64 + nt * 8 + cp;
                float a0 = acc[mt][nt][2 * h + 0];
                float a1 = acc[mt][nt][2 * h + 1];
                if (MODE == 0) {
                    if (n < Cout)     dst[(size_t)m * Cout + n]     = a0 + bias[n];
                    if (n + 1 < Cout) dst[(size_t)m * Cout + n + 1] = a1 + bias[n + 1];
                } else {
                    if (n < Cout) {
                        float v = tanhf(a0 + bias[n]);
                        dst[(size_t)m * Cout + n] = v;
                        out2[(size_t)m * Cout + n] = v;
                    }
                    if (n + 1 < Cout) {
                        float v = tanhf(a1 + bias[n + 1]);
                        dst[(size_t)m * Cout + n + 1] = v;
                        out2[(size_t)m * Cout + n + 1] = v;
                    }
                }
            }
        }
    }
}

// ---------------- launch ----------------
extern "C" void kernel_launch(void* const* d_in, const int* in_sizes, int n_in,
                              void* d_out, int out_size) {
    const int*   x   = (const int*)  d_in[0];
    const float* emb = (const float*)d_in[1];
    const float* w1  = (const float*)d_in[2];
    const float* b1  = (const float*)d_in[3];
    const float* w2  = (const float*)d_in[4];
    const float* b2  = (const float*)d_in[5];
    const float* w3  = (const float*)d_in[6];
    const float* b3  = (const float*)d_in[7];
    const float* g1  = (const float*)d_in[8];
    const float* be1 = (const float*)d_in[9];
    const float* g2  = (const float*)d_in[10];
    const float* be2 = (const float*)d_in[11];
    float* out = (float*)d_out;

    const int gemmSmem = GSTAGES * STG * 2;   // 98304 bytes
    cudaFuncSetAttribute(k_gram_t<false>,          cudaFuncAttributeMaxDynamicSharedMemorySize, gemmSmem);
    cudaFuncSetAttribute(k_gram_t<true>,           cudaFuncAttributeMaxDynamicSharedMemorySize, gemmSmem);
    cudaFuncSetAttribute(k_conv_gemm<13,0,false>,  cudaFuncAttributeMaxDynamicSharedMemorySize, gemmSmem);
    cudaFuncSetAttribute(k_conv_gemm<5,0,false>,   cudaFuncAttributeMaxDynamicSharedMemorySize, gemmSmem);
    cudaFuncSetAttribute(k_conv_gemm<1,1,true>,    cudaFuncAttributeMaxDynamicSharedMemorySize, gemmSmem);

    __half *eh, *el, *w1h, *w1l, *w2h, *w2l, *w3h, *w3l;
    __half *h1h, *h1l, *h2h, *h2l, *fh, *fl;
    float *h1p, *h2p, *finp, *m1p, *i1p, *m2p, *i2p;
    cudaGetSymbolAddress((void**)&eh,  g_Eh);
    cudaGetSymbolAddress((void**)&el,  g_El);
    cudaGetSymbolAddress((void**)&w1h, g_W1h);
    cudaGetSymbolAddress((void**)&w1l, g_W1l);
    cudaGetSymbolAddress((void**)&w2h, g_W2h);
    cudaGetSymbolAddress((void**)&w2l, g_W2l);
    cudaGetSymbolAddress((void**)&w3h, g_W3h);
    cudaGetSymbolAddress((void**)&w3l, g_W3l);
    cudaGetSymbolAddress((void**)&h1h, g_h1h);
    cudaGetSymbolAddress((void**)&h1l, g_h1l);
    cudaGetSymbolAddress((void**)&h2h, g_h2h);
    cudaGetSymbolAddress((void**)&h2l, g_h2l);
    cudaGetSymbolAddress((void**)&fh,  g_Fnh);
    cudaGetSymbolAddress((void**)&fl,  g_Fnl);
    cudaGetSymbolAddress((void**)&h1p, g_h1);
    cudaGetSymbolAddress((void**)&h2p, g_h2);
    cudaGetSymbolAddress((void**)&finp, g_final);
    cudaGetSymbolAddress((void**)&m1p, g_mean1);
    cudaGetSymbolAddress((void**)&i1p, g_istd1);
    cudaGetSymbolAddress((void**)&m2p, g_mean2);
    cudaGetSymbolAddress((void**)&i2p, g_istd2);

    // ---- prologue on the main (capture) stream ----
    k_scales<<<(VOCAB * 32 + 255) / 256, 256>>>(emb);
    k_gather<<<BATCH, 256>>>(x, emb);
    k_prep_w<<<1024, 256>>>(w1, w2, w3);
    k_padzero<<<16, 256>>>();

    // ---- fork: big input Gram runs concurrently with the conv chain ----
    cudaStream_t s2;
    cudaStreamCreateWithFlags(&s2, cudaStreamNonBlocking);
    cudaEvent_t evFork, evJoin;
    cudaEventCreateWithFlags(&evFork, cudaEventDisableTiming);
    cudaEventCreateWithFlags(&evJoin, cudaEventDisableTiming);

    cudaEventRecord(evFork, 0);
    cudaStreamWaitEvent(s2, evFork, 0);

    // input Gram: fp16 2-term (A-lo dropped) on side stream
    k_gram_t<false><<<528, 128, gemmSmem, s2>>>(eh, el, BW_E, BW_E / GBK, out + HOUT);
    cudaEventRecord(evJoin, s2);

    // ---- conv chain on the main stream (conv1/conv2 2-term, conv3 3-term) ----
    {
        dim3 g(3, M1 / GBM);
        k_conv_gemm<13,0,false><<<g, 128, gemmSmem>>>(eh, el, w1h, w1l, (K1 + GBK - 1) / GBK, BW_E, K1, C1, b1, h1p, nullptr);
    }
    k_bnstat_p<<<dim3(10, 32), 256>>>(h1p, M1, C1);
    k_bnstat_r<<<2, 256>>>(C1, 1.f / M1, m1p, i1p);
    k_bnapply<<<2048, 256>>>(h1p, h1h, h1l, m1p, i1p, g1, be1, M1, C1, L1o, 4);

    {
        dim3 g(5, M2 / GBM);
        k_conv_gemm<5,0,false><<<g, 128, gemmSmem>>>(h1h, h1l, w2h, w2l, (K1 + GBK - 1) / GBK, BW_H1, K1, C2, b2, h2p, nullptr);
    }
    k_bnstat_p<<<dim3(19, 32), 256>>>(h2p, M2, C2);
    k_bnstat_r<<<3, 256>>>(C2, 1.f / M2, m2p, i2p);
    k_bnapply<<<2048, 256>>>(h2p, h2h, h2l, m2p, i2p, g2, be2, M2, C2, L2o, 8);

    {
        dim3 g(1, BATCH / GBM);
        k_conv_gemm<1,1,true><<<g, 128, gemmSmem>>>(h2h, h2l, w3h, w3l, K3 / GBK, BW_H2, K3, C3, b3, finp, out);
    }
    k_norm<<<BATCH * 32 / 256, 256>>>();

    // hidden Gram: 3-term 128-tiles on main stream
    k_gram_t<true><<<528, 128, gemmSmem>>>(fh, fl, KPAD_F, KPAD_F / GBK, out + HOUT + NPAIRS);

    // ---- join side stream back into the main stream ----
    cudaStreamWaitEvent(0, evJoin, 0);

    cudaEventDestroy(evFork);
    cudaEventDestroy(evJoin);
    cudaStreamDestroy(s2);
}

// round 12
// speedup vs baseline: 1.5451x; 1.1927x over previous
#include <cuda_runtime.h>
#include <cuda_fp16.h>
#include <cstdint>
#include <math.h>

// ---------------- problem constants ----------------
#define BATCH 4096
#define LSEQ  28
#define VOCAB 32000
#define DIM   300
#define BW_E  8704            // per-batch row: 300 front pad + 8400 data + 4 back pad
#define KPAD_F 128
#define K1    1504            // conv1/conv2 GEMM K (1500 padded)
#define K3    3008            // conv3 GEMM K (3000 padded)
#define BW_H1 3904            // 13*300 + 4
#define BW_H2 3008            // 5*600 + 8
#define L1o   13
#define C1    300
#define L2o   5
#define C2    600
#define C3    100
#define M1    (BATCH*L1o)     // 53248 = 416*128
#define M2    (BATCH*L2o)     // 20480 = 160*128
#define NPAIRS 8386560
#define HOUT  (BATCH*C3)

// ---------------- scratch ----------------
__device__ __half g_Eh[(size_t)BATCH*BW_E + 64];
__device__ __half g_El[(size_t)BATCH*BW_E + 64];
__device__ __half g_W1h[384*K1], g_W1l[384*K1];
__device__ __half g_W2h[640*K1], g_W2l[640*K1];
__device__ __half g_W3h[128*K3], g_W3l[128*K3];
__device__ float g_h1[(size_t)M1*C1];
__device__ float g_h2[(size_t)M2*C2];
__device__ __half g_h1h[(size_t)BATCH*BW_H1 + 64], g_h1l[(size_t)BATCH*BW_H1 + 64];
__device__ __half g_h2h[(size_t)BATCH*BW_H2 + 64], g_h2l[(size_t)BATCH*BW_H2 + 64];
__device__ float g_final[BATCH*C3];
__device__ __half g_Fnh[BATCH*KPAD_F], g_Fnl[BATCH*KPAD_F];
__device__ float g_scales[VOCAB];
__device__ float g_mean1[C1], g_istd1[C1];
__device__ float g_mean2[C2], g_istd2[C2];
__device__ float g_part[32*640*2];

// ---------------- embedding renorm scales ----------------
__global__ void k_scales(const float* __restrict__ emb) {
    int warp = (blockIdx.x * blockDim.x + threadIdx.x) >> 5;
    int lane = threadIdx.x & 31;
    if (warp >= VOCAB) return;
    const float* row = emb + (size_t)warp * DIM;
    float s = 0.f;
    for (int d = lane; d < DIM; d += 32) { float v = row[d]; s += v * v; }
    #pragma unroll
    for (int o = 16; o; o >>= 1) s += __shfl_xor_sync(0xffffffffu, s, o);
    if (lane == 0) g_scales[warp] = fminf(1.f, 1.f / (sqrtf(s) + 1e-7f));
}

// ---------------- gather into position-major E_T (+ fp16 split, + pads) ----------------
__global__ void k_gather(const int* __restrict__ x, const float* __restrict__ emb) {
    __shared__ int   tok[LSEQ];
    __shared__ float sc[LSEQ];
    int b = blockIdx.x, t = threadIdx.x;
    bool is64 = (x[1] == 0 && x[3] == 0 && x[5] == 0 && x[7] == 0);
    if (t < LSEQ) {
        int v = is64 ? x[(b * LSEQ + t) * 2] : x[b * LSEQ + t];
        tok[t] = v;
        sc[t]  = g_scales[v];
    }
    __syncthreads();
    __half* dH = g_Eh + (size_t)b * BW_E;
    __half* dL = g_El + (size_t)b * BW_E;
    const __half z = __float2half_rn(0.f);
    for (int i = t; i < 304; i += blockDim.x) {
        int o = (i < 300) ? i : (8400 + i);
        dH[o] = z; dL[o] = z;
    }
    for (int i = t; i < DIM * LSEQ; i += blockDim.x) {
        int l = i / DIM, ci = i - l * DIM;
        float v = emb[(size_t)tok[l] * DIM + ci] * sc[l];
        __half h = __float2half_rn(v);
        dH[300 + i] = h;
        dL[300 + i] = __float2half_rn(v - __half2float(h));
    }
}

// ---------------- weight prep ----------------
__global__ void k_prep_w(const float* __restrict__ w1, const float* __restrict__ w2,
                         const float* __restrict__ w3) {
    const int n1 = 384 * K1, n2 = 640 * K1, n3 = 128 * K3;
    int total = n1 + n2 + n3;
    for (int idx = blockIdx.x * blockDim.x + threadIdx.x; idx < total; idx += gridDim.x * blockDim.x) {
        int i = idx;
        if (i < n1) {
            int n = i / K1, k = i - n * K1;
            int kk = k / 300, ci = k - kk * 300;
            float v = (n < C1 && kk < 5) ? w1[n * 1500 + ci * 5 + kk] : 0.f;
            __half h = __float2half_rn(v);
            g_W1h[i] = h;
            g_W1l[i] = __float2half_rn(v - __half2float(h));
            continue;
        }
        i -= n1;
        if (i < n2) {
            int n = i / K1, k = i - n * K1;
            int kk = k / 300, ci = k - kk * 300;
            float v = (n < C2 && kk < 5) ? w2[n * 1500 + ci * 5 + kk] : 0.f;
            __half h = __float2half_rn(v);
            g_W2h[i] = h;
            g_W2l[i] = __float2half_rn(v - __half2float(h));
            continue;
        }
        i -= n2;
        {
            int n = i / K3, k = i - n * K3;
            int kk = k / 600, ci = k - kk * 600;
            float v = (n < C3 && kk < 5) ? w3[n * 3000 + ci * 5 + kk] : 0.f;
            __half h = __float2half_rn(v);
            g_W3h[i] = h;
            g_W3l[i] = __float2half_rn(v - __half2float(h));
        }
    }
}

// ---------------- zero tail pads ----------------
__global__ void k_padzero() {
    int b = blockIdx.x * blockDim.x + threadIdx.x;
    const __half z = __float2half_rn(0.f);
    if (b < BATCH) {
        #pragma unroll
        for (int i = 0; i < 4; i++) {
            g_h1h[(size_t)b * BW_H1 + 3900 + i] = z;
            g_h1l[(size_t)b * BW_H1 + 3900 + i] = z;
        }
        #pragma unroll
        for (int i = 0; i < 8; i++) {
            g_h2h[(size_t)b * BW_H2 + 3000 + i] = z;
            g_h2l[(size_t)b * BW_H2 + 3000 + i] = z;
        }
    }
    if (b < 64) {
        g_Eh[(size_t)BATCH * BW_E + b]  = z;
        g_El[(size_t)BATCH * BW_E + b]  = z;
        g_h1h[(size_t)BATCH * BW_H1 + b] = z;
        g_h1l[(size_t)BATCH * BW_H1 + b] = z;
        g_h2h[(size_t)BATCH * BW_H2 + b] = z;
        g_h2l[(size_t)BATCH * BW_H2 + b] = z;
    }
}

// ---------------- BN stats ----------------
__global__ void k_bnstat_p(const float* __restrict__ h, int M, int C) {
    int lane = threadIdx.x & 31;
    int w = threadIdx.x >> 5;
    int c = blockIdx.x * 32 + lane;
    int chunk = blockIdx.y;
    int rpc = M >> 5;
    float s = 0.f, s2 = 0.f;
    if (c < C) {
        int r1 = (chunk + 1) * rpc;
        for (int r = chunk * rpc + w; r < r1; r += 8) {
            float v = h[(size_t)r * C + c];
            s += v; s2 += v * v;
        }
    }
    __shared__ float sh[8][32][2];
    sh[w][lane][0] = s; sh[w][lane][1] = s2;
    __syncthreads();
    if (threadIdx.x < 32) {
        float S = 0.f, S2 = 0.f;
        #pragma unroll
        for (int i = 0; i < 8; i++) { S += sh[i][threadIdx.x][0]; S2 += sh[i][threadIdx.x][1]; }
        int cc = blockIdx.x * 32 + threadIdx.x;
        if (cc < C) {
            g_part[(chunk * 640 + cc) * 2 + 0] = S;
            g_part[(chunk * 640 + cc) * 2 + 1] = S2;
        }
    }
}

__global__ void k_bnstat_r(int C, float invN, float* __restrict__ mean, float* __restrict__ istd) {
    int c = blockIdx.x * blockDim.x + threadIdx.x;
    if (c >= C) return;
    float S = 0.f, S2 = 0.f;
    for (int ch = 0; ch < 32; ch++) {
        S  += g_part[(ch * 640 + c) * 2 + 0];
        S2 += g_part[(ch * 640 + c) * 2 + 1];
    }
    float m = S * invN;
    mean[c] = m;
    istd[c] = rsqrtf(S2 * invN - m * m + 1e-5f);
}

// ---------------- BN apply + ReLU + fp16 split into padded T layout ----------------
__global__ void k_bnapply(const float* __restrict__ h, __half* __restrict__ oh,
                          __half* __restrict__ ol,
                          const float* __restrict__ mean, const float* __restrict__ istd,
                          const float* __restrict__ gamma, const float* __restrict__ beta,
                          int M, int C, int lout, int pad) {
    size_t total = (size_t)M * C;
    size_t stride = (size_t)gridDim.x * blockDim.x;
    for (size_t idx = (size_t)blockIdx.x * blockDim.x + threadIdx.x; idx < total; idx += stride) {
        int m = (int)(idx / C), c = (int)(idx - (size_t)m * C);
        float v = (h[idx] - mean[c]) * istd[c] * gamma[c] + beta[c];
        v = fmaxf(v, 0.f);
        size_t off = idx + (size_t)pad * (m / lout);
        __half hi = __float2half_rn(v);
        oh[off] = hi;
        ol[off] = __float2half_rn(v - __half2float(hi));
    }
}

// ---------------- row-normalize final -> fp16 hi/lo ----------------
__global__ void k_norm() {
    int gw = (blockIdx.x * blockDim.x + threadIdx.x) >> 5;
    int lane = threadIdx.x & 31;
    if (gw >= BATCH) return;
    const float* f = g_final + gw * C3;
    float s = 0.f;
    for (int c = lane; c < C3; c += 32) { float v = f[c]; s += v * v; }
    #pragma unroll
    for (int o = 16; o; o >>= 1) s += __shfl_xor_sync(0xffffffffu, s, o);
    float n = sqrtf(s);
    __half* oh = g_Fnh + gw * KPAD_F;
    __half* ol = g_Fnl + gw * KPAD_F;
    for (int c = lane; c < C3; c += 32) {
        float v = f[c] / n;
        __half h = __float2half_rn(v);
        oh[c] = h;
        ol[c] = __float2half_rn(v - __half2float(h));
    }
    for (int c = C3 + lane; c < KPAD_F; c += 32) {
        oh[c] = __float2half_rn(0.f);
        ol[c] = __float2half_rn(0.f);
    }
}

// ================= HMMA GEMM machinery (split-fp16, swizzled smem) =================
// CTA 128x128, 128 threads = 4 warps of 64x64. 3-stage cp.async pipeline, Kc=32.
// TERMS=3: C = Ah*Bh + Ah*Bl + Al*Bh  (err ~2^-22)
// TERMS=2: C = Ah*Bh + Ah*Bl          (err ~2^-12, A-lo never loaded)
// TERMS=1: C = Ah*Bh                  (err ~2^-11.5, only hi matrices loaded)
#define GBM 128
#define GBK 32
#define GSTAGES 3
#define MSZ (128*32)

__device__ __forceinline__ void cp16(__half* dst, const __half* src) {
    unsigned a = (unsigned)__cvta_generic_to_shared(dst);
    asm volatile("cp.async.cg.shared.global [%0], [%1], 16;\n" :: "r"(a), "l"(src));
}
__device__ __forceinline__ void ldm4(unsigned* r, const __half* p) {
    unsigned a = (unsigned)__cvta_generic_to_shared(p);
    asm volatile("ldmatrix.sync.aligned.m8n8.x4.shared.b16 {%0,%1,%2,%3}, [%4];\n"
                 : "=r"(r[0]), "=r"(r[1]), "=r"(r[2]), "=r"(r[3]) : "r"(a));
}
__device__ __forceinline__ void mma16816(float* d, const unsigned* a, const unsigned* b) {
    asm volatile("mma.sync.aligned.m16n8k16.row.col.f32.f16.f16.f32 "
                 "{%0,%1,%2,%3}, {%4,%5,%6,%7}, {%8,%9}, {%0,%1,%2,%3};\n"
                 : "+f"(d[0]), "+f"(d[1]), "+f"(d[2]), "+f"(d[3])
                 : "r"(a[0]), "r"(a[1]), "r"(a[2]), "r"(a[3]), "r"(b[0]), "r"(b[1]));
}
__device__ __forceinline__ int swz(int row, int chunk) {
    return row * 32 + ((chunk ^ ((row >> 1) & 3)) << 3);
}

// slot layout per stage: [Ah][Al if TERMS==3][Bh][Bl if TERMS>=2]; stage size (TERMS+1)*MSZ
template<int LA, int TERMS>
__device__ __forceinline__ void load_stage(__half* dst,
        const __half* Ah, const __half* Al,
        const __half* Bh, const __half* Bl,
        int i0, int j0, int kc, int bwA, int bwB, int t) {
    const int B_HI = (TERMS == 3) ? 2 * MSZ : MSZ;
    #pragma unroll
    for (int q = 0; q < 4; q++) {
        int idx = t + q * 128;
        int row = idx >> 2, c = idx & 3;
        int so = swz(row, c);
        int ra = i0 + row;
        int ba = ra / LA, la = ra - ba * LA;
        size_t goA = (size_t)ba * bwA + la * 600 + kc + c * 8;
        size_t goB = (size_t)(j0 + row) * bwB + kc + c * 8;
        cp16(dst + so, Ah + goA);
        if (TERMS == 3) cp16(dst + MSZ + so, Al + goA);
        cp16(dst + B_HI + so, Bh + goB);
        if (TERMS >= 2) cp16(dst + B_HI + MSZ + so, Bl + goB);
    }
}

template<int LA, int TERMS>
__device__ __forceinline__ void gemm_core(
        const __half* Ah, const __half* Al,
        const __half* Bh, const __half* Bl,
        int i0, int j0, int bwA, int bwB, int kIters,
        __half* sm, int t, float acc[4][8][4]) {
    const int STG_T = (TERMS + 1) * MSZ;
    const int B_HI  = (TERMS == 3) ? 2 * MSZ : MSZ;
    int lane = t & 31, wid = t >> 5;
    int wm = wid & 1, wn = wid >> 1;      // 2x2 warp grid, 64x64 per warp
    int lr = lane & 15, lc = (lane >> 4) << 3;

    #pragma unroll
    for (int s = 0; s < GSTAGES - 1; s++) {
        if (s < kIters) load_stage<LA, TERMS>(sm + s * STG_T, Ah, Al, Bh, Bl, i0, j0, s * GBK, bwA, bwB, t);
        asm volatile("cp.async.commit_group;\n");
    }
    for (int it = 0; it < kIters; it++) {
        asm volatile("cp.async.wait_group %0;\n" :: "n"(GSTAGES - 2));
        __syncthreads();
        int nxt = it + GSTAGES - 1;
        if (nxt < kIters) load_stage<LA, TERMS>(sm + (nxt % GSTAGES) * STG_T, Ah, Al, Bh, Bl, i0, j0, nxt * GBK, bwA, bwB, t);
        asm volatile("cp.async.commit_group;\n");

        const __half* buf = sm + (it % GSTAGES) * STG_T;
        const __half* sAh = buf;
        const __half* sAl = buf + MSZ;          // valid only TERMS==3
        const __half* sBh = buf + B_HI;
        const __half* sBl = buf + B_HI + MSZ;   // valid only TERMS>=2

        #pragma unroll
        for (int ks = 0; ks < GBK; ks += 16) {
            unsigned ah[4][4], al[4][4], bh[8][2], bl[8][2];
            int cl = (ks + lc) >> 3;
            #pragma unroll
            for (int mt = 0; mt < 4; mt++) {
                int rA = wm * 64 + mt * 16 + lr;
                ldm4(ah[mt], sAh + swz(rA, cl));
                if (TERMS == 3) ldm4(al[mt], sAl + swz(rA, cl));
            }
            #pragma unroll
            for (int bt = 0; bt < 4; bt++) {
                int rB = wn * 64 + bt * 16 + lr;
                unsigned r4[4];
                ldm4(r4, sBh + swz(rB, cl));
                bh[2 * bt][0] = r4[0]; bh[2 * bt][1] = r4[2];
                bh[2 * bt + 1][0] = r4[1]; bh[2 * bt + 1][1] = r4[3];
                if (TERMS >= 2) {
                    ldm4(r4, sBl + swz(rB, cl));
                    bl[2 * bt][0] = r4[0]; bl[2 * bt][1] = r4[2];
                    bl[2 * bt + 1][0] = r4[1]; bl[2 * bt + 1][1] = r4[3];
                }
            }
            #pragma unroll
            for (int mt = 0; mt < 4; mt++)
                #pragma unroll
                for (int nt = 0; nt < 8; nt++) {
                    mma16816(acc[mt][nt], ah[mt], bh[nt]);
                    if (TERMS >= 2) mma16816(acc[mt][nt], ah[mt], bl[nt]);
                    if (TERMS == 3) mma16816(acc[mt][nt], al[mt], bh[nt]);
                }
        }
        // NOTE: no trailing __syncthreads needed — the next iteration's loads target
        // buffer (it+3)%3 and are issued only after the top-of-loop barrier, which
        // already orders all warps past this iteration's compute.
    }
    __syncthreads();
}

// ---------------- symmetric Gram, triu-packed output ----------------
template<int TERMS>
__global__ __launch_bounds__(128, 2)
void k_gram_t(const __half* __restrict__ Xhi, const __half* __restrict__ Xlo,
              int ldk, int kIters, float* __restrict__ out) {
    extern __shared__ __half sm[];
    int p = blockIdx.x;
    int ti = 0, rem = 32;
    while (p >= rem) { p -= rem; rem--; ti++; }
    int tj = ti + p;
    const int i0 = ti * GBM, j0 = tj * GBM;

    int t = threadIdx.x;
    float acc[4][8][4];
    #pragma unroll
    for (int mt = 0; mt < 4; mt++)
        #pragma unroll
        for (int nt = 0; nt < 8; nt++)
            #pragma unroll
            for (int e = 0; e < 4; e++) acc[mt][nt][e] = 0.f;

    gemm_core<1, TERMS>(Xhi, Xlo, Xhi, Xlo, i0, j0, ldk, ldk, kIters, sm, t, acc);

    int lane = t & 31, wid = t >> 5;
    int wm = wid & 1, wn = wid >> 1;
    int r = lane >> 2, cp = (lane & 3) * 2;
    #pragma unroll
    for (int mt = 0; mt < 4; mt++) {
        #pragma unroll
        for (int h = 0; h < 2; h++) {
            int i = i0 + wm * 64 + mt * 16 + r + h * 8;
            int base = i * (8191 - i) / 2 - i - 1;
            #pragma unroll
            for (int nt = 0; nt < 8; nt++) {
                int j = j0 + wn * 64 + nt * 8 + cp;
                if (j > i)     out[base + j]     = acc[mt][nt][2 * h + 0];
                if (j + 1 > i) out[base + j + 1] = acc[mt][nt][2 * h + 1];
            }
        }
    }
}

// ---------------- conv GEMM: implicit im2col; MODE 0: bias; MODE 1: bias+tanh -> dst & out2 ----------------
template<int LA, int MODE, int TERMS>
__global__ __launch_bounds__(128, 2)
void k_conv_gemm(const __half* __restrict__ Ah, const __half* __restrict__ Al,
                 const __half* __restrict__ Bh, const __half* __restrict__ Bl,
                 int kIters, int bwA, int bwB, int Cout,
                 const float* __restrict__ bias, float* __restrict__ dst, float* __restrict__ out2) {
    extern __shared__ __half sm[];
    const int n0 = blockIdx.x * GBM, m0 = blockIdx.y * GBM;

    int t = threadIdx.x;
    float acc[4][8][4];
    #pragma unroll
    for (int mt = 0; mt < 4; mt++)
        #pragma unroll
        for (int nt = 0; nt < 8; nt++)
            #pragma unroll
            for (int e = 0; e < 4; e++) acc[mt][nt][e] = 0.f;

    gemm_core<LA, TERMS>(Ah, Al, Bh, Bl, m0, n0, bwA, bwB, kIters, sm, t, acc);

    int lane = t & 31, wid = t >> 5;
    int wm = wid & 1, wn = wid >> 1;
    int r = lane >> 2, cp = (lane & 3) * 2;
    #pragma unroll
    for (int mt = 0; mt < 4; mt++) {
        #pragma unroll
        for (int h = 0; h < 2; h++) {
            int m = m0 + wm * 64 + mt * 16 + r + h * 8;
            #pragma unroll
            for (int nt = 0; nt < 8; nt++) {
                int n = n0 + wn * 64 + nt * 8 + cp;
                float a0 = acc[mt][nt][2 * h + 0];
                float a1 = acc[mt][nt][2 * h + 1];
                if (MODE == 0) {
                    if (n < Cout)     dst[(size_t)m * Cout + n]     = a0 + bias[n];
                    if (n + 1 < Cout) dst[(size_t)m * Cout + n + 1] = a1 + bias[n + 1];
                } else {
                    if (n < Cout) {
                        float v = tanhf(a0 + bias[n]);
                        dst[(size_t)m * Cout + n] = v;
                        out2[(size_t)m * Cout + n] = v;
                    }
                    if (n + 1 < Cout) {
                        float v = tanhf(a1 + bias[n + 1]);
                        dst[(size_t)m * Cout + n + 1] = v;
                        out2[(size_t)m * Cout + n + 1] = v;
                    }
                }
            }
        }
    }
}

// ---------------- launch ----------------
extern "C" void kernel_launch(void* const* d_in, const int* in_sizes, int n_in,
                              void* d_out, int out_size) {
    const int*   x   = (const int*)  d_in[0];
    const float* emb = (const float*)d_in[1];
    const float* w1  = (const float*)d_in[2];
    const float* b1  = (const float*)d_in[3];
    const float* w2  = (const float*)d_in[4];
    const float* b2  = (const float*)d_in[5];
    const float* w3  = (const float*)d_in[6];
    const float* b3  = (const float*)d_in[7];
    const float* g1  = (const float*)d_in[8];
    const float* be1 = (const float*)d_in[9];
    const float* g2  = (const float*)d_in[10];
    const float* be2 = (const float*)d_in[11];
    float* out = (float*)d_out;

    const int smem1 = GSTAGES * 2 * MSZ * 2;   // TERMS=1: 49152
    const int smem2 = GSTAGES * 3 * MSZ * 2;   // TERMS=2: 73728
    const int smem3 = GSTAGES * 4 * MSZ * 2;   // TERMS=3: 98304
    cudaFuncSetAttribute(k_gram_t<1>,           cudaFuncAttributeMaxDynamicSharedMemorySize, smem1);
    cudaFuncSetAttribute(k_gram_t<3>,           cudaFuncAttributeMaxDynamicSharedMemorySize, smem3);
    cudaFuncSetAttribute(k_conv_gemm<13,0,2>,   cudaFuncAttributeMaxDynamicSharedMemorySize, smem2);
    cudaFuncSetAttribute(k_conv_gemm<5,0,2>,    cudaFuncAttributeMaxDynamicSharedMemorySize, smem2);
    cudaFuncSetAttribute(k_conv_gemm<1,1,3>,    cudaFuncAttributeMaxDynamicSharedMemorySize, smem3);

    __half *eh, *el, *w1h, *w1l, *w2h, *w2l, *w3h, *w3l;
    __half *h1h, *h1l, *h2h, *h2l, *fh, *fl;
    float *h1p, *h2p, *finp, *m1p, *i1p, *m2p, *i2p;
    cudaGetSymbolAddress((void**)&eh,  g_Eh);
    cudaGetSymbolAddress((void**)&el,  g_El);
    cudaGetSymbolAddress((void**)&w1h, g_W1h);
    cudaGetSymbolAddress((void**)&w1l, g_W1l);
    cudaGetSymbolAddress((void**)&w2h, g_W2h);
    cudaGetSymbolAddress((void**)&w2l, g_W2l);
    cudaGetSymbolAddress((void**)&w3h, g_W3h);
    cudaGetSymbolAddress((void**)&w3l, g_W3l);
    cudaGetSymbolAddress((void**)&h1h, g_h1h);
    cudaGetSymbolAddress((void**)&h1l, g_h1l);
    cudaGetSymbolAddress((void**)&h2h, g_h2h);
    cudaGetSymbolAddress((void**)&h2l, g_h2l);
    cudaGetSymbolAddress((void**)&fh,  g_Fnh);
    cudaGetSymbolAddress((void**)&fl,  g_Fnl);
    cudaGetSymbolAddress((void**)&h1p, g_h1);
    cudaGetSymbolAddress((void**)&h2p, g_h2);
    cudaGetSymbolAddress((void**)&finp, g_final);
    cudaGetSymbolAddress((void**)&m1p, g_mean1);
    cudaGetSymbolAddress((void**)&i1p, g_istd1);
    cudaGetSymbolAddress((void**)&m2p, g_mean2);
    cudaGetSymbolAddress((void**)&i2p, g_istd2);

    // ---- prologue on the main (capture) stream ----
    k_scales<<<(VOCAB * 32 + 255) / 256, 256>>>(emb);
    k_gather<<<BATCH, 256>>>(x, emb);
    k_prep_w<<<1024, 256>>>(w1, w2, w3);
    k_padzero<<<16, 256>>>();

    // ---- fork: big input Gram runs concurrently with the conv chain ----
    cudaStream_t s2;
    cudaStreamCreateWithFlags(&s2, cudaStreamNonBlocking);
    cudaEvent_t evFork, evJoin;
    cudaEventCreateWithFlags(&evFork, cudaEventDisableTiming);
    cudaEventCreateWithFlags(&evJoin, cudaEventDisableTiming);

    cudaEventRecord(evFork, 0);
    cudaStreamWaitEvent(s2, evFork, 0);

    // input Gram: 1-term plain fp16 on side stream
    k_gram_t<1><<<528, 128, smem1, s2>>>(eh, el, BW_E, BW_E / GBK, out + HOUT);
    cudaEventRecord(evJoin, s2);

    // ---- conv chain on the main stream (conv1/conv2 2-term, conv3 3-term) ----
    {
        dim3 g(3, M1 / GBM);
        k_conv_gemm<13,0,2><<<g, 128, smem2>>>(eh, el, w1h, w1l, (K1 + GBK - 1) / GBK, BW_E, K1, C1, b1, h1p, nullptr);
    }
    k_bnstat_p<<<dim3(10, 32), 256>>>(h1p, M1, C1);
    k_bnstat_r<<<2, 256>>>(C1, 1.f / M1, m1p, i1p);
    k_bnapply<<<2048, 256>>>(h1p, h1h, h1l, m1p, i1p, g1, be1, M1, C1, L1o, 4);

    {
        dim3 g(5, M2 / GBM);
        k_conv_gemm<5,0,2><<<g, 128, smem2>>>(h1h, h1l, w2h, w2l, (K1 + GBK - 1) / GBK, BW_H1, K1, C2, b2, h2p, nullptr);
    }
    k_bnstat_p<<<dim3(19, 32), 256>>>(h2p, M2, C2);
    k_bnstat_r<<<3, 256>>>(C2, 1.f / M2, m2p, i2p);
    k_bnapply<<<2048, 256>>>(h2p, h2h, h2l, m2p, i2p, g2, be2, M2, C2, L2o, 8);

    {
        dim3 g(1, BATCH / GBM);
        k_conv_gemm<1,1,3><<<g, 128, smem3>>>(h2h, h2l, w3h, w3l, K3 / GBK, BW_H2, K3, C3, b3, finp, out);
    }
    k_norm<<<BATCH * 32 / 256, 256>>>();

    // hidden Gram: 3-term 128-tiles on main stream
    k_gram_t<3><<<528, 128, smem3>>>(fh, fl, KPAD_F, KPAD_F / GBK, out + HOUT + NPAIRS);

    // ---- join side stream back into the main stream ----
    cudaStreamWaitEvent(0, evJoin, 0);

    cudaEventDestroy(evFork);
    cudaEventDestroy(evJoin);
    cudaStreamDestroy(s2);
}

// round 13
// speedup vs baseline: 1.8651x; 1.2071x over previous
#include <cuda_runtime.h>
#include <cuda_fp16.h>
#include <cstdint>
#include <math.h>

// ---------------- problem constants ----------------
#define BATCH 4096
#define LSEQ  28
#define VOCAB 32000
#define DIM   300
#define BW_E  8704            // per-batch row: 300 front pad + 8400 data + 4 back pad
#define KPAD_F 128
#define K1    1504            // conv1/conv2 GEMM K (1500 padded)
#define K3    3008            // conv3 GEMM K (3000 padded)
#define BW_H1 3904            // 13*300 + 4
#define BW_H2 3008            // 5*600 + 8
#define L1o   13
#define C1    300
#define L2o   5
#define C2    600
#define C3    100
#define M1    (BATCH*L1o)     // 53248 = 416*128
#define M2    (BATCH*L2o)     // 20480 = 160*128
#define NPAIRS 8386560
#define HOUT  (BATCH*C3)

// ---------------- scratch ----------------
__device__ __half g_Eh[(size_t)BATCH*BW_E + 64];
__device__ __half g_El[(size_t)BATCH*BW_E + 64];
__device__ __half g_W1h[384*K1], g_W1l[384*K1];
__device__ __half g_W2h[640*K1], g_W2l[640*K1];
__device__ __half g_W3h[128*K3], g_W3l[128*K3];
__device__ float g_h1[(size_t)M1*C1];
__device__ float g_h2[(size_t)M2*C2];
__device__ __half g_h1h[(size_t)BATCH*BW_H1 + 64], g_h1l[(size_t)BATCH*BW_H1 + 64];
__device__ __half g_h2h[(size_t)BATCH*BW_H2 + 64], g_h2l[(size_t)BATCH*BW_H2 + 64];
__device__ float g_final[BATCH*C3];
__device__ __half g_Fnh[BATCH*KPAD_F], g_Fnl[BATCH*KPAD_F];
__device__ float g_scales[VOCAB];
__device__ float g_mean1[C1], g_istd1[C1];
__device__ float g_mean2[C2], g_istd2[C2];
__device__ float g_part[32*640*2];

// ---------------- embedding renorm scales ----------------
__global__ void k_scales(const float* __restrict__ emb) {
    int warp = (blockIdx.x * blockDim.x + threadIdx.x) >> 5;
    int lane = threadIdx.x & 31;
    if (warp >= VOCAB) return;
    const float* row = emb + (size_t)warp * DIM;
    float s = 0.f;
    for (int d = lane; d < DIM; d += 32) { float v = row[d]; s += v * v; }
    #pragma unroll
    for (int o = 16; o; o >>= 1) s += __shfl_xor_sync(0xffffffffu, s, o);
    if (lane == 0) g_scales[warp] = fminf(1.f, 1.f / (sqrtf(s) + 1e-7f));
}

// ---------------- gather into position-major E_T (+ fp16 split, + pads) ----------------
__global__ void k_gather(const int* __restrict__ x, const float* __restrict__ emb) {
    __shared__ int   tok[LSEQ];
    __shared__ float sc[LSEQ];
    int b = blockIdx.x, t = threadIdx.x;
    bool is64 = (x[1] == 0 && x[3] == 0 && x[5] == 0 && x[7] == 0);
    if (t < LSEQ) {
        int v = is64 ? x[(b * LSEQ + t) * 2] : x[b * LSEQ + t];
        tok[t] = v;
        sc[t]  = g_scales[v];
    }
    __syncthreads();
    __half* dH = g_Eh + (size_t)b * BW_E;
    __half* dL = g_El + (size_t)b * BW_E;
    const __half z = __float2half_rn(0.f);
    for (int i = t; i < 304; i += blockDim.x) {
        int o = (i < 300) ? i : (8400 + i);
        dH[o] = z; dL[o] = z;
    }
    for (int i = t; i < DIM * LSEQ; i += blockDim.x) {
        int l = i / DIM, ci = i - l * DIM;
        float v = emb[(size_t)tok[l] * DIM + ci] * sc[l];
        __half h = __float2half_rn(v);
        dH[300 + i] = h;
        dL[300 + i] = __float2half_rn(v - __half2float(h));
    }
}

// ---------------- weight prep ----------------
__global__ void k_prep_w(const float* __restrict__ w1, const float* __restrict__ w2,
                         const float* __restrict__ w3) {
    const int n1 = 384 * K1, n2 = 640 * K1, n3 = 128 * K3;
    int total = n1 + n2 + n3;
    for (int idx = blockIdx.x * blockDim.x + threadIdx.x; idx < total; idx += gridDim.x * blockDim.x) {
        int i = idx;
        if (i < n1) {
            int n = i / K1, k = i - n * K1;
            int kk = k / 300, ci = k - kk * 300;
            float v = (n < C1 && kk < 5) ? w1[n * 1500 + ci * 5 + kk] : 0.f;
            __half h = __float2half_rn(v);
            g_W1h[i] = h;
            g_W1l[i] = __float2half_rn(v - __half2float(h));
            continue;
        }
        i -= n1;
        if (i < n2) {
            int n = i / K1, k = i - n * K1;
            int kk = k / 300, ci = k - kk * 300;
            float v = (n < C2 && kk < 5) ? w2[n * 1500 + ci * 5 + kk] : 0.f;
            __half h = __float2half_rn(v);
            g_W2h[i] = h;
            g_W2l[i] = __float2half_rn(v - __half2float(h));
            continue;
        }
        i -= n2;
        {
            int n = i / K3, k = i - n * K3;
            int kk = k / 600, ci = k - kk * 600;
            float v = (n < C3 && kk < 5) ? w3[n * 3000 + ci * 5 + kk] : 0.f;
            __half h = __float2half_rn(v);
            g_W3h[i] = h;
            g_W3l[i] = __float2half_rn(v - __half2float(h));
        }
    }
}

// ---------------- zero tail pads ----------------
__global__ void k_padzero() {
    int b = blockIdx.x * blockDim.x + threadIdx.x;
    const __half z = __float2half_rn(0.f);
    if (b < BATCH) {
        #pragma unroll
        for (int i = 0; i < 4; i++) {
            g_h1h[(size_t)b * BW_H1 + 3900 + i] = z;
            g_h1l[(size_t)b * BW_H1 + 3900 + i] = z;
        }
        #pragma unroll
        for (int i = 0; i < 8; i++) {
            g_h2h[(size_t)b * BW_H2 + 3000 + i] = z;
            g_h2l[(size_t)b * BW_H2 + 3000 + i] = z;
        }
    }
    if (b < 64) {
        g_Eh[(size_t)BATCH * BW_E + b]  = z;
        g_El[(size_t)BATCH * BW_E + b]  = z;
        g_h1h[(size_t)BATCH * BW_H1 + b] = z;
        g_h1l[(size_t)BATCH * BW_H1 + b] = z;
        g_h2h[(size_t)BATCH * BW_H2 + b] = z;
        g_h2l[(size_t)BATCH * BW_H2 + b] = z;
    }
}

// ---------------- BN stats ----------------
__global__ void k_bnstat_p(const float* __restrict__ h, int M, int C) {
    int lane = threadIdx.x & 31;
    int w = threadIdx.x >> 5;
    int c = blockIdx.x * 32 + lane;
    int chunk = blockIdx.y;
    int rpc = M >> 5;
    float s = 0.f, s2 = 0.f;
    if (c < C) {
        int r1 = (chunk + 1) * rpc;
        for (int r = chunk * rpc + w; r < r1; r += 8) {
            float v = h[(size_t)r * C + c];
            s += v; s2 += v * v;
        }
    }
    __shared__ float sh[8][32][2];
    sh[w][lane][0] = s; sh[w][lane][1] = s2;
    __syncthreads();
    if (threadIdx.x < 32) {
        float S = 0.f, S2 = 0.f;
        #pragma unroll
        for (int i = 0; i < 8; i++) { S += sh[i][threadIdx.x][0]; S2 += sh[i][threadIdx.x][1]; }
        int cc = blockIdx.x * 32 + threadIdx.x;
        if (cc < C) {
            g_part[(chunk * 640 + cc) * 2 + 0] = S;
            g_part[(chunk * 640 + cc) * 2 + 1] = S2;
        }
    }
}

__global__ void k_bnstat_r(int C, float invN, float* __restrict__ mean, float* __restrict__ istd) {
    int c = blockIdx.x * blockDim.x + threadIdx.x;
    if (c >= C) return;
    float S = 0.f, S2 = 0.f;
    for (int ch = 0; ch < 32; ch++) {
        S  += g_part[(ch * 640 + c) * 2 + 0];
        S2 += g_part[(ch * 640 + c) * 2 + 1];
    }
    float m = S * invN;
    mean[c] = m;
    istd[c] = rsqrtf(S2 * invN - m * m + 1e-5f);
}

// ---------------- BN apply + ReLU + fp16 split into padded T layout ----------------
__global__ void k_bnapply(const float* __restrict__ h, __half* __restrict__ oh,
                          __half* __restrict__ ol,
                          const float* __restrict__ mean, const float* __restrict__ istd,
                          const float* __restrict__ gamma, const float* __restrict__ beta,
                          int M, int C, int lout, int pad) {
    size_t total = (size_t)M * C;
    size_t stride = (size_t)gridDim.x * blockDim.x;
    for (size_t idx = (size_t)blockIdx.x * blockDim.x + threadIdx.x; idx < total; idx += stride) {
        int m = (int)(idx / C), c = (int)(idx - (size_t)m * C);
        float v = (h[idx] - mean[c]) * istd[c] * gamma[c] + beta[c];
        v = fmaxf(v, 0.f);
        size_t off = idx + (size_t)pad * (m / lout);
        __half hi = __float2half_rn(v);
        oh[off] = hi;
        ol[off] = __float2half_rn(v - __half2float(hi));
    }
}

// ---------------- row-normalize final -> fp16 hi/lo ----------------
__global__ void k_norm() {
    int gw = (blockIdx.x * blockDim.x + threadIdx.x) >> 5;
    int lane = threadIdx.x & 31;
    if (gw >= BATCH) return;
    const float* f = g_final + gw * C3;
    float s = 0.f;
    for (int c = lane; c < C3; c += 32) { float v = f[c]; s += v * v; }
    #pragma unroll
    for (int o = 16; o; o >>= 1) s += __shfl_xor_sync(0xffffffffu, s, o);
    float n = sqrtf(s);
    __half* oh = g_Fnh + gw * KPAD_F;
    __half* ol = g_Fnl + gw * KPAD_F;
    for (int c = lane; c < C3; c += 32) {
        float v = f[c] / n;
        __half h = __float2half_rn(v);
        oh[c] = h;
        ol[c] = __float2half_rn(v - __half2float(h));
    }
    for (int c = C3 + lane; c < KPAD_F; c += 32) {
        oh[c] = __float2half_rn(0.f);
        ol[c] = __float2half_rn(0.f);
    }
}

// ================= HMMA GEMM machinery (split-fp16, swizzled smem) =================
// CTA 128x128, 128 threads = 4 warps of 64x64. 3-stage cp.async pipeline, Kc=32.
// TERMS=3: C = Ah*Bh + Ah*Bl + Al*Bh  (err ~2^-22)
// TERMS=2: C = Ah*Bh + Ah*Bl          (err ~2^-12, A-lo never loaded)
// TERMS=1: C = Ah*Bh                  (err ~2^-11.5, only hi matrices loaded)
#define GBM 128
#define GBK 32
#define GSTAGES 3
#define MSZ (128*32)

__device__ __forceinline__ void cp16(__half* dst, const __half* src) {
    unsigned a = (unsigned)__cvta_generic_to_shared(dst);
    asm volatile("cp.async.cg.shared.global [%0], [%1], 16;\n" :: "r"(a), "l"(src));
}
__device__ __forceinline__ void ldm4(unsigned* r, const __half* p) {
    unsigned a = (unsigned)__cvta_generic_to_shared(p);
    asm volatile("ldmatrix.sync.aligned.m8n8.x4.shared.b16 {%0,%1,%2,%3}, [%4];\n"
                 : "=r"(r[0]), "=r"(r[1]), "=r"(r[2]), "=r"(r[3]) : "r"(a));
}
__device__ __forceinline__ void mma16816(float* d, const unsigned* a, const unsigned* b) {
    asm volatile("mma.sync.aligned.m16n8k16.row.col.f32.f16.f16.f32 "
                 "{%0,%1,%2,%3}, {%4,%5,%6,%7}, {%8,%9}, {%0,%1,%2,%3};\n"
                 : "+f"(d[0]), "+f"(d[1]), "+f"(d[2]), "+f"(d[3])
                 : "r"(a[0]), "r"(a[1]), "r"(a[2]), "r"(a[3]), "r"(b[0]), "r"(b[1]));
}
__device__ __forceinline__ int swz(int row, int chunk) {
    return row * 32 + ((chunk ^ ((row >> 1) & 3)) << 3);
}

// slot layout per stage: [Ah][Al if TERMS==3][Bh][Bl if TERMS>=2]; stage size (TERMS+1)*MSZ
template<int LA, int TERMS>
__device__ __forceinline__ void load_stage(__half* dst,
        const __half* Ah, const __half* Al,
        const __half* Bh, const __half* Bl,
        int i0, int j0, int kc, int bwA, int bwB, int t) {
    const int B_HI = (TERMS == 3) ? 2 * MSZ : MSZ;
    #pragma unroll
    for (int q = 0; q < 4; q++) {
        int idx = t + q * 128;
        int row = idx >> 2, c = idx & 3;
        int so = swz(row, c);
        int ra = i0 + row;
        int ba = ra / LA, la = ra - ba * LA;
        size_t goA = (size_t)ba * bwA + la * 600 + kc + c * 8;
        size_t goB = (size_t)(j0 + row) * bwB + kc + c * 8;
        cp16(dst + so, Ah + goA);
        if (TERMS == 3) cp16(dst + MSZ + so, Al + goA);
        cp16(dst + B_HI + so, Bh + goB);
        if (TERMS >= 2) cp16(dst + B_HI + MSZ + so, Bl + goB);
    }
}

template<int LA, int TERMS>
__device__ __forceinline__ void gemm_core(
        const __half* Ah, const __half* Al,
        const __half* Bh, const __half* Bl,
        int i0, int j0, int bwA, int bwB, int kIters,
        __half* sm, int t, float acc[4][8][4]) {
    const int STG_T = (TERMS + 1) * MSZ;
    const int B_HI  = (TERMS == 3) ? 2 * MSZ : MSZ;
    int lane = t & 31, wid = t >> 5;
    int wm = wid & 1, wn = wid >> 1;      // 2x2 warp grid, 64x64 per warp
    int lr = lane & 15, lc = (lane >> 4) << 3;

    #pragma unroll
    for (int s = 0; s < GSTAGES - 1; s++) {
        if (s < kIters) load_stage<LA, TERMS>(sm + s * STG_T, Ah, Al, Bh, Bl, i0, j0, s * GBK, bwA, bwB, t);
        asm volatile("cp.async.commit_group;\n");
    }
    for (int it = 0; it < kIters; it++) {
        asm volatile("cp.async.wait_group %0;\n" :: "n"(GSTAGES - 2));
        __syncthreads();
        int nxt = it + GSTAGES - 1;
        if (nxt < kIters) load_stage<LA, TERMS>(sm + (nxt % GSTAGES) * STG_T, Ah, Al, Bh, Bl, i0, j0, nxt * GBK, bwA, bwB, t);
        asm volatile("cp.async.commit_group;\n");

        const __half* buf = sm + (it % GSTAGES) * STG_T;
        const __half* sAh = buf;
        const __half* sAl = buf + MSZ;          // valid only TERMS==3
        const __half* sBh = buf + B_HI;
        const __half* sBl = buf + B_HI + MSZ;   // valid only TERMS>=2

        #pragma unroll
        for (int ks = 0; ks < GBK; ks += 16) {
            unsigned ah[4][4], al[4][4], bh[8][2], bl[8][2];
            int cl = (ks + lc) >> 3;
            #pragma unroll
            for (int mt = 0; mt < 4; mt++) {
                int rA = wm * 64 + mt * 16 + lr;
                ldm4(ah[mt], sAh + swz(rA, cl));
                if (TERMS == 3) ldm4(al[mt], sAl + swz(rA, cl));
            }
            #pragma unroll
            for (int bt = 0; bt < 4; bt++) {
                int rB = wn * 64 + bt * 16 + lr;
                unsigned r4[4];
                ldm4(r4, sBh + swz(rB, cl));
                bh[2 * bt][0] = r4[0]; bh[2 * bt][1] = r4[2];
                bh[2 * bt + 1][0] = r4[1]; bh[2 * bt + 1][1] = r4[3];
                if (TERMS >= 2) {
                    ldm4(r4, sBl + swz(rB, cl));
                    bl[2 * bt][0] = r4[0]; bl[2 * bt][1] = r4[2];
                    bl[2 * bt + 1][0] = r4[1]; bl[2 * bt + 1][1] = r4[3];
                }
            }
            #pragma unroll
            for (int mt = 0; mt < 4; mt++)
                #pragma unroll
                for (int nt = 0; nt < 8; nt++) {
                    mma16816(acc[mt][nt], ah[mt], bh[nt]);
                    if (TERMS >= 2) mma16816(acc[mt][nt], ah[mt], bl[nt]);
                    if (TERMS == 3) mma16816(acc[mt][nt], al[mt], bh[nt]);
                }
        }
        // no trailing __syncthreads — next iteration's loads are gated by the
        // top-of-loop barrier, which already orders all warps past this compute.
    }
    __syncthreads();
}

// ---------------- symmetric Gram, triu-packed output ----------------
template<int TERMS>
__global__ __launch_bounds__(128, 2)
void k_gram_t(const __half* __restrict__ Xhi, const __half* __restrict__ Xlo,
              int ldk, int kIters, float* __restrict__ out) {
    extern __shared__ __half sm[];
    int p = blockIdx.x;
    int ti = 0, rem = 32;
    while (p >= rem) { p -= rem; rem--; ti++; }
    int tj = ti + p;
    const int i0 = ti * GBM, j0 = tj * GBM;

    int t = threadIdx.x;
    float acc[4][8][4];
    #pragma unroll
    for (int mt = 0; mt < 4; mt++)
        #pragma unroll
        for (int nt = 0; nt < 8; nt++)
            #pragma unroll
            for (int e = 0; e < 4; e++) acc[mt][nt][e] = 0.f;

    gemm_core<1, TERMS>(Xhi, Xlo, Xhi, Xlo, i0, j0, ldk, ldk, kIters, sm, t, acc);

    int lane = t & 31, wid = t >> 5;
    int wm = wid & 1, wn = wid >> 1;
    int r = lane >> 2, cp = (lane & 3) * 2;
    #pragma unroll
    for (int mt = 0; mt < 4; mt++) {
        #pragma unroll
        for (int h = 0; h < 2; h++) {
            int i = i0 + wm * 64 + mt * 16 + r + h * 8;
            int base = i * (8191 - i) / 2 - i - 1;
            #pragma unroll
            for (int nt = 0; nt < 8; nt++) {
                int j = j0 + wn * 64 + nt * 8 + cp;
                if (j > i)     out[base + j]     = acc[mt][nt][2 * h + 0];
                if (j + 1 > i) out[base + j + 1] = acc[mt][nt][2 * h + 1];
            }
        }
    }
}

// ---------------- conv GEMM: implicit im2col; MODE 0: bias; MODE 1: bias+tanh -> dst & out2 ----------------
template<int LA, int MODE, int TERMS>
__global__ __launch_bounds__(128, 2)
void k_conv_gemm(const __half* __restrict__ Ah, const __half* __restrict__ Al,
                 const __half* __restrict__ Bh, const __half* __restrict__ Bl,
                 int kIters, int bwA, int bwB, int Cout,
                 const float* __restrict__ bias, float* __restrict__ dst, float* __restrict__ out2) {
    extern __shared__ __half sm[];
    const int n0 = blockIdx.x * GBM, m0 = blockIdx.y * GBM;

    int t = threadIdx.x;
    float acc[4][8][4];
    #pragma unroll
    for (int mt = 0; mt < 4; mt++)
        #pragma unroll
        for (int nt = 0; nt < 8; nt++)
            #pragma unroll
            for (int e = 0; e < 4; e++) acc[mt][nt][e] = 0.f;

    gemm_core<LA, TERMS>(Ah, Al, Bh, Bl, m0, n0, bwA, bwB, kIters, sm, t, acc);

    int lane = t & 31, wid = t >> 5;
    int wm = wid & 1, wn = wid >> 1;
    int r = lane >> 2, cp = (lane & 3) * 2;
    #pragma unroll
    for (int mt = 0; mt < 4; mt++) {
        #pragma unroll
        for (int h = 0; h < 2; h++) {
            int m = m0 + wm * 64 + mt * 16 + r + h * 8;
            #pragma unroll
            for (int nt = 0; nt < 8; nt++) {
                int n = n0 + wn * 64 + nt * 8 + cp;
                float a0 = acc[mt][nt][2 * h + 0];
                float a1 = acc[mt][nt][2 * h + 1];
                if (MODE == 0) {
                    if (n < Cout)     dst[(size_t)m * Cout + n]     = a0 + bias[n];
                    if (n + 1 < Cout) dst[(size_t)m * Cout + n + 1] = a1 + bias[n + 1];
                } else {
                    if (n < Cout) {
                        float v = tanhf(a0 + bias[n]);
                        dst[(size_t)m * Cout + n] = v;
                        out2[(size_t)m * Cout + n] = v;
                    }
                    if (n + 1 < Cout) {
                        float v = tanhf(a1 + bias[n + 1]);
                        dst[(size_t)m * Cout + n + 1] = v;
                        out2[(size_t)m * Cout + n + 1] = v;
                    }
                }
            }
        }
    }
}

// ---------------- launch ----------------
extern "C" void kernel_launch(void* const* d_in, const int* in_sizes, int n_in,
                              void* d_out, int out_size) {
    const int*   x   = (const int*)  d_in[0];
    const float* emb = (const float*)d_in[1];
    const float* w1  = (const float*)d_in[2];
    const float* b1  = (const float*)d_in[3];
    const float* w2  = (const float*)d_in[4];
    const float* b2  = (const float*)d_in[5];
    const float* w3  = (const float*)d_in[6];
    const float* b3  = (const float*)d_in[7];
    const float* g1  = (const float*)d_in[8];
    const float* be1 = (const float*)d_in[9];
    const float* g2  = (const float*)d_in[10];
    const float* be2 = (const float*)d_in[11];
    float* out = (float*)d_out;

    const int smem1 = GSTAGES * 2 * MSZ * 2;   // TERMS=1: 49152
    const int smem3 = GSTAGES * 4 * MSZ * 2;   // TERMS=3: 98304
    cudaFuncSetAttribute(k_gram_t<1>,           cudaFuncAttributeMaxDynamicSharedMemorySize, smem1);
    cudaFuncSetAttribute(k_gram_t<3>,           cudaFuncAttributeMaxDynamicSharedMemorySize, smem3);
    cudaFuncSetAttribute(k_conv_gemm<13,0,1>,   cudaFuncAttributeMaxDynamicSharedMemorySize, smem1);
    cudaFuncSetAttribute(k_conv_gemm<5,0,1>,    cudaFuncAttributeMaxDynamicSharedMemorySize, smem1);
    cudaFuncSetAttribute(k_conv_gemm<1,1,3>,    cudaFuncAttributeMaxDynamicSharedMemorySize, smem3);

    __half *eh, *el, *w1h, *w1l, *w2h, *w2l, *w3h, *w3l;
    __half *h1h, *h1l, *h2h, *h2l, *fh, *fl;
    float *h1p, *h2p, *finp, *m1p, *i1p, *m2p, *i2p;
    cudaGetSymbolAddress((void**)&eh,  g_Eh);
    cudaGetSymbolAddress((void**)&el,  g_El);
    cudaGetSymbolAddress((void**)&w1h, g_W1h);
    cudaGetSymbolAddress((void**)&w1l, g_W1l);
    cudaGetSymbolAddress((void**)&w2h, g_W2h);
    cudaGetSymbolAddress((void**)&w2l, g_W2l);
    cudaGetSymbolAddress((void**)&w3h, g_W3h);
    cudaGetSymbolAddress((void**)&w3l, g_W3l);
    cudaGetSymbolAddress((void**)&h1h, g_h1h);
    cudaGetSymbolAddress((void**)&h1l, g_h1l);
    cudaGetSymbolAddress((void**)&h2h, g_h2h);
    cudaGetSymbolAddress((void**)&h2l, g_h2l);
    cudaGetSymbolAddress((void**)&fh,  g_Fnh);
    cudaGetSymbolAddress((void**)&fl,  g_Fnl);
    cudaGetSymbolAddress((void**)&h1p, g_h1);
    cudaGetSymbolAddress((void**)&h2p, g_h2);
    cudaGetSymbolAddress((void**)&finp, g_final);
    cudaGetSymbolAddress((void**)&m1p, g_mean1);
    cudaGetSymbolAddress((void**)&i1p, g_istd1);
    cudaGetSymbolAddress((void**)&m2p, g_mean2);
    cudaGetSymbolAddress((void**)&i2p, g_istd2);

    // ---- prologue on the main (capture) stream ----
    k_scales<<<(VOCAB * 32 + 255) / 256, 256>>>(emb);
    k_gather<<<BATCH, 256>>>(x, emb);
    k_prep_w<<<1024, 256>>>(w1, w2, w3);
    k_padzero<<<16, 256>>>();

    // ---- fork: big input Gram runs concurrently with the conv chain ----
    cudaStream_t s2;
    cudaStreamCreateWithFlags(&s2, cudaStreamNonBlocking);
    cudaEvent_t evFork, evJoin;
    cudaEventCreateWithFlags(&evFork, cudaEventDisableTiming);
    cudaEventCreateWithFlags(&evJoin, cudaEventDisableTiming);

    cudaEventRecord(evFork, 0);
    cudaStreamWaitEvent(s2, evFork, 0);

    // input Gram: 1-term plain fp16 on side stream
    k_gram_t<1><<<528, 128, smem1, s2>>>(eh, el, BW_E, BW_E / GBK, out + HOUT);
    cudaEventRecord(evJoin, s2);

    // ---- conv chain on the main stream (conv1/conv2 1-term, conv3 3-term) ----
    {
        dim3 g(3, M1 / GBM);
        k_conv_gemm<13,0,1><<<g, 128, smem1>>>(eh, el, w1h, w1l, (K1 + GBK - 1) / GBK, BW_E, K1, C1, b1, h1p, nullptr);
    }
    k_bnstat_p<<<dim3(10, 32), 256>>>(h1p, M1, C1);
    k_bnstat_r<<<2, 256>>>(C1, 1.f / M1, m1p, i1p);
    k_bnapply<<<2048, 256>>>(h1p, h1h, h1l, m1p, i1p, g1, be1, M1, C1, L1o, 4);

    {
        dim3 g(5, M2 / GBM);
        k_conv_gemm<5,0,1><<<g, 128, smem1>>>(h1h, h1l, w2h, w2l, (K1 + GBK - 1) / GBK, BW_H1, K1, C2, b2, h2p, nullptr);
    }
    k_bnstat_p<<<dim3(19, 32), 256>>>(h2p, M2, C2);
    k_bnstat_r<<<3, 256>>>(C2, 1.f / M2, m2p, i2p);
    k_bnapply<<<2048, 256>>>(h2p, h2h, h2l, m2p, i2p, g2, be2, M2, C2, L2o, 8);

    {
        dim3 g(1, BATCH / GBM);
        k_conv_gemm<1,1,3><<<g, 128, smem3>>>(h2h, h2l, w3h, w3l, K3 / GBK, BW_H2, K3, C3, b3, finp, out);
    }
    k_norm<<<BATCH * 32 / 256, 256>>>();

    // hidden Gram: 3-term 128-tiles on main stream
    k_gram_t<3><<<528, 128, smem3>>>(fh, fl, KPAD_F, KPAD_F / GBK, out + HOUT + NPAIRS);

    // ---- join side stream back into the main stream ----
    cudaStreamWaitEvent(0, evJoin, 0);

    cudaEventDestroy(evFork);
    cudaEventDestroy(evJoin);
    cudaStreamDestroy(s2);
}

// round 14
// speedup vs baseline: 1.9553x; 1.0484x over previous
#include <cuda_runtime.h>
#include <cuda_fp16.h>
#include <cstdint>
#include <math.h>

// ---------------- problem constants ----------------
#define BATCH 4096
#define LSEQ  28
#define VOCAB 32000
#define DIM   300
#define BW_E  8704            // per-batch row: 300 front pad + 8400 data + 4 back pad
#define KPAD_F 128
#define K1    1504            // conv1/conv2 GEMM K (1500 padded)
#define K3    3008            // conv3 GEMM K (3000 padded)
#define BW_H1 3904            // 13*300 + 4
#define BW_H2 3008            // 5*600 + 8
#define L1o   13
#define C1    300
#define L2o   5
#define C2    600
#define C3    100
#define M1    (BATCH*L1o)     // 53248 = 416*128
#define M2    (BATCH*L2o)     // 20480 = 160*128
#define NPAIRS 8386560
#define HOUT  (BATCH*C3)

// ---------------- scratch (lo-buffers kept ONLY where actually read) ----------------
__device__ __half g_Eh[(size_t)BATCH*BW_E + 64];
__device__ __half g_W1h[384*K1];
__device__ __half g_W2h[640*K1];
__device__ __half g_W3h[128*K3], g_W3l[128*K3];
__device__ float g_h1[(size_t)M1*C1];
__device__ float g_h2[(size_t)M2*C2];
__device__ __half g_h1h[(size_t)BATCH*BW_H1 + 64];
__device__ __half g_h2h[(size_t)BATCH*BW_H2 + 64], g_h2l[(size_t)BATCH*BW_H2 + 64];
__device__ float g_final[BATCH*C3];
__device__ __half g_Fnh[BATCH*KPAD_F], g_Fnl[BATCH*KPAD_F];
__device__ float g_scales[VOCAB];
__device__ float g_mean1[C1], g_istd1[C1];
__device__ float g_mean2[C2], g_istd2[C2];
__device__ float g_part[32*640*2];

// ---------------- embedding renorm scales ----------------
__global__ void k_scales(const float* __restrict__ emb) {
    int warp = (blockIdx.x * blockDim.x + threadIdx.x) >> 5;
    int lane = threadIdx.x & 31;
    if (warp >= VOCAB) return;
    const float* row = emb + (size_t)warp * DIM;
    float s = 0.f;
    for (int d = lane; d < DIM; d += 32) { float v = row[d]; s += v * v; }
    #pragma unroll
    for (int o = 16; o; o >>= 1) s += __shfl_xor_sync(0xffffffffu, s, o);
    if (lane == 0) g_scales[warp] = fminf(1.f, 1.f / (sqrtf(s) + 1e-7f));
}

// ---------------- gather into position-major E_T (hi only) ----------------
__global__ void k_gather(const int* __restrict__ x, const float* __restrict__ emb) {
    __shared__ int   tok[LSEQ];
    __shared__ float sc[LSEQ];
    int b = blockIdx.x, t = threadIdx.x;
    bool is64 = (x[1] == 0 && x[3] == 0 && x[5] == 0 && x[7] == 0);
    if (t < LSEQ) {
        int v = is64 ? x[(b * LSEQ + t) * 2] : x[b * LSEQ + t];
        tok[t] = v;
        sc[t]  = g_scales[v];
    }
    __syncthreads();
    __half* dH = g_Eh + (size_t)b * BW_E;
    const __half z = __float2half_rn(0.f);
    for (int i = t; i < 304; i += blockDim.x) {
        int o = (i < 300) ? i : (8400 + i);
        dH[o] = z;
    }
    for (int i = t; i < DIM * LSEQ; i += blockDim.x) {
        int l = i / DIM, ci = i - l * DIM;
        float v = emb[(size_t)tok[l] * DIM + ci] * sc[l];
        dH[300 + i] = __float2half_rn(v);
    }
}

// ---------------- weight prep (w1/w2 hi only; w3 split) ----------------
__global__ void k_prep_w(const float* __restrict__ w1, const float* __restrict__ w2,
                         const float* __restrict__ w3) {
    const int n1 = 384 * K1, n2 = 640 * K1, n3 = 128 * K3;
    int total = n1 + n2 + n3;
    for (int idx = blockIdx.x * blockDim.x + threadIdx.x; idx < total; idx += gridDim.x * blockDim.x) {
        int i = idx;
        if (i < n1) {
            int n = i / K1, k = i - n * K1;
            int kk = k / 300, ci = k - kk * 300;
            float v = (n < C1 && kk < 5) ? w1[n * 1500 + ci * 5 + kk] : 0.f;
            g_W1h[i] = __float2half_rn(v);
            continue;
        }
        i -= n1;
        if (i < n2) {
            int n = i / K1, k = i - n * K1;
            int kk = k / 300, ci = k - kk * 300;
            float v = (n < C2 && kk < 5) ? w2[n * 1500 + ci * 5 + kk] : 0.f;
            g_W2h[i] = __float2half_rn(v);
            continue;
        }
        i -= n2;
        {
            int n = i / K3, k = i - n * K3;
            int kk = k / 600, ci = k - kk * 600;
            float v = (n < C3 && kk < 5) ? w3[n * 3000 + ci * 5 + kk] : 0.f;
            __half h = __float2half_rn(v);
            g_W3h[i] = h;
            g_W3l[i] = __float2half_rn(v - __half2float(h));
        }
    }
}

// ---------------- zero tail pads ----------------
__global__ void k_padzero() {
    int b = blockIdx.x * blockDim.x + threadIdx.x;
    const __half z = __float2half_rn(0.f);
    if (b < BATCH) {
        #pragma unroll
        for (int i = 0; i < 4; i++) {
            g_h1h[(size_t)b * BW_H1 + 3900 + i] = z;
        }
        #pragma unroll
        for (int i = 0; i < 8; i++) {
            g_h2h[(size_t)b * BW_H2 + 3000 + i] = z;
            g_h2l[(size_t)b * BW_H2 + 3000 + i] = z;
        }
    }
    if (b < 64) {
        g_Eh[(size_t)BATCH * BW_E + b]   = z;
        g_h1h[(size_t)BATCH * BW_H1 + b] = z;
        g_h2h[(size_t)BATCH * BW_H2 + b] = z;
        g_h2l[(size_t)BATCH * BW_H2 + b] = z;
    }
}

// ---------------- BN stats ----------------
__global__ void k_bnstat_p(const float* __restrict__ h, int M, int C) {
    int lane = threadIdx.x & 31;
    int w = threadIdx.x >> 5;
    int c = blockIdx.x * 32 + lane;
    int chunk = blockIdx.y;
    int rpc = M >> 5;
    float s = 0.f, s2 = 0.f;
    if (c < C) {
        int r1 = (chunk + 1) * rpc;
        for (int r = chunk * rpc + w; r < r1; r += 8) {
            float v = h[(size_t)r * C + c];
            s += v; s2 += v * v;
        }
    }
    __shared__ float sh[8][32][2];
    sh[w][lane][0] = s; sh[w][lane][1] = s2;
    __syncthreads();
    if (threadIdx.x < 32) {
        float S = 0.f, S2 = 0.f;
        #pragma unroll
        for (int i = 0; i < 8; i++) { S += sh[i][threadIdx.x][0]; S2 += sh[i][threadIdx.x][1]; }
        int cc = blockIdx.x * 32 + threadIdx.x;
        if (cc < C) {
            g_part[(chunk * 640 + cc) * 2 + 0] = S;
            g_part[(chunk * 640 + cc) * 2 + 1] = S2;
        }
    }
}

__global__ void k_bnstat_r(int C, float invN, float* __restrict__ mean, float* __restrict__ istd) {
    int c = blockIdx.x * blockDim.x + threadIdx.x;
    if (c >= C) return;
    float S = 0.f, S2 = 0.f;
    for (int ch = 0; ch < 32; ch++) {
        S  += g_part[(ch * 640 + c) * 2 + 0];
        S2 += g_part[(ch * 640 + c) * 2 + 1];
    }
    float m = S * invN;
    mean[c] = m;
    istd[c] = rsqrtf(S2 * invN - m * m + 1e-5f);
}

// ---------------- BN apply + ReLU + fp16 (optionally split) into padded T layout ----------------
__global__ void k_bnapply(const float* __restrict__ h, __half* __restrict__ oh,
                          __half* __restrict__ ol,
                          const float* __restrict__ mean, const float* __restrict__ istd,
                          const float* __restrict__ gamma, const float* __restrict__ beta,
                          int M, int C, int lout, int pad) {
    size_t total = (size_t)M * C;
    size_t stride = (size_t)gridDim.x * blockDim.x;
    for (size_t idx = (size_t)blockIdx.x * blockDim.x + threadIdx.x; idx < total; idx += stride) {
        int m = (int)(idx / C), c = (int)(idx - (size_t)m * C);
        float v = (h[idx] - mean[c]) * istd[c] * gamma[c] + beta[c];
        v = fmaxf(v, 0.f);
        size_t off = idx + (size_t)pad * (m / lout);
        __half hi = __float2half_rn(v);
        oh[off] = hi;
        if (ol) ol[off] = __float2half_rn(v - __half2float(hi));
    }
}

// ---------------- row-normalize final -> fp16 hi/lo ----------------
__global__ void k_norm() {
    int gw = (blockIdx.x * blockDim.x + threadIdx.x) >> 5;
    int lane = threadIdx.x & 31;
    if (gw >= BATCH) return;
    const float* f = g_final + gw * C3;
    float s = 0.f;
    for (int c = lane; c < C3; c += 32) { float v = f[c]; s += v * v; }
    #pragma unroll
    for (int o = 16; o; o >>= 1) s += __shfl_xor_sync(0xffffffffu, s, o);
    float n = sqrtf(s);
    __half* oh = g_Fnh + gw * KPAD_F;
    __half* ol = g_Fnl + gw * KPAD_F;
    for (int c = lane; c < C3; c += 32) {
        float v = f[c] / n;
        __half h = __float2half_rn(v);
        oh[c] = h;
        ol[c] = __float2half_rn(v - __half2float(h));
    }
    for (int c = C3 + lane; c < KPAD_F; c += 32) {
        oh[c] = __float2half_rn(0.f);
        ol[c] = __float2half_rn(0.f);
    }
}

// ================= HMMA GEMM machinery (split-fp16, swizzled smem) =================
// CTA 128x128, 128 threads = 4 warps of 64x64. 3-stage cp.async pipeline, Kc=32.
// TERMS=3: C = Ah*Bh + Ah*Bl + Al*Bh ; TERMS=2: + Ah*Bl ; TERMS=1: Ah*Bh only
#define GBM 128
#define GBK 32
#define GSTAGES 3
#define MSZ (128*32)

__device__ __forceinline__ void cp16(__half* dst, const __half* src) {
    unsigned a = (unsigned)__cvta_generic_to_shared(dst);
    asm volatile("cp.async.cg.shared.global [%0], [%1], 16;\n" :: "r"(a), "l"(src));
}
__device__ __forceinline__ void ldm4(unsigned* r, const __half* p) {
    unsigned a = (unsigned)__cvta_generic_to_shared(p);
    asm volatile("ldmatrix.sync.aligned.m8n8.x4.shared.b16 {%0,%1,%2,%3}, [%4];\n"
                 : "=r"(r[0]), "=r"(r[1]), "=r"(r[2]), "=r"(r[3]) : "r"(a));
}
__device__ __forceinline__ void mma16816(float* d, const unsigned* a, const unsigned* b) {
    asm volatile("mma.sync.aligned.m16n8k16.row.col.f32.f16.f16.f32 "
                 "{%0,%1,%2,%3}, {%4,%5,%6,%7}, {%8,%9}, {%0,%1,%2,%3};\n"
                 : "+f"(d[0]), "+f"(d[1]), "+f"(d[2]), "+f"(d[3])
                 : "r"(a[0]), "r"(a[1]), "r"(a[2]), "r"(a[3]), "r"(b[0]), "r"(b[1]));
}
__device__ __forceinline__ int swz(int row, int chunk) {
    return row * 32 + ((chunk ^ ((row >> 1) & 3)) << 3);
}

template<int LA, int TERMS>
__device__ __forceinline__ void load_stage(__half* dst,
        const __half* Ah, const __half* Al,
        const __half* Bh, const __half* Bl,
        int i0, int j0, int kc, int bwA, int bwB, int t) {
    const int B_HI = (TERMS == 3) ? 2 * MSZ : MSZ;
    #pragma unroll
    for (int q = 0; q < 4; q++) {
        int idx = t + q * 128;
        int row = idx >> 2, c = idx & 3;
        int so = swz(row, c);
        int ra = i0 + row;
        int ba = ra / LA, la = ra - ba * LA;
        size_t goA = (size_t)ba * bwA + la * 600 + kc + c * 8;
        size_t goB = (size_t)(j0 + row) * bwB + kc + c * 8;
        cp16(dst + so, Ah + goA);
        if (TERMS == 3) cp16(dst + MSZ + so, Al + goA);
        cp16(dst + B_HI + so, Bh + goB);
        if (TERMS >= 2) cp16(dst + B_HI + MSZ + so, Bl + goB);
    }
}

template<int LA, int TERMS>
__device__ __forceinline__ void gemm_core(
        const __half* Ah, const __half* Al,
        const __half* Bh, const __half* Bl,
        int i0, int j0, int bwA, int bwB, int kIters,
        __half* sm, int t, float acc[4][8][4]) {
    const int STG_T = (TERMS + 1) * MSZ;
    const int B_HI  = (TERMS == 3) ? 2 * MSZ : MSZ;
    int lane = t & 31, wid = t >> 5;
    int wm = wid & 1, wn = wid >> 1;
    int lr = lane & 15, lc = (lane >> 4) << 3;

    #pragma unroll
    for (int s = 0; s < GSTAGES - 1; s++) {
        if (s < kIters) load_stage<LA, TERMS>(sm + s * STG_T, Ah, Al, Bh, Bl, i0, j0, s * GBK, bwA, bwB, t);
        asm volatile("cp.async.commit_group;\n");
    }
    for (int it = 0; it < kIters; it++) {
        asm volatile("cp.async.wait_group %0;\n" :: "n"(GSTAGES - 2));
        __syncthreads();
        int nxt = it + GSTAGES - 1;
        if (nxt < kIters) load_stage<LA, TERMS>(sm + (nxt % GSTAGES) * STG_T, Ah, Al, Bh, Bl, i0, j0, nxt * GBK, bwA, bwB, t);
        asm volatile("cp.async.commit_group;\n");

        const __half* buf = sm + (it % GSTAGES) * STG_T;
        const __half* sAh = buf;
        const __half* sAl = buf + MSZ;
        const __half* sBh = buf + B_HI;
        const __half* sBl = buf + B_HI + MSZ;

        #pragma unroll
        for (int ks = 0; ks < GBK; ks += 16) {
            unsigned ah[4][4], al[4][4], bh[8][2], bl[8][2];
            int cl = (ks + lc) >> 3;
            #pragma unroll
            for (int mt = 0; mt < 4; mt++) {
                int rA = wm * 64 + mt * 16 + lr;
                ldm4(ah[mt], sAh + swz(rA, cl));
                if (TERMS == 3) ldm4(al[mt], sAl + swz(rA, cl));
            }
            #pragma unroll
            for (int bt = 0; bt < 4; bt++) {
                int rB = wn * 64 + bt * 16 + lr;
                unsigned r4[4];
                ldm4(r4, sBh + swz(rB, cl));
                bh[2 * bt][0] = r4[0]; bh[2 * bt][1] = r4[2];
                bh[2 * bt + 1][0] = r4[1]; bh[2 * bt + 1][1] = r4[3];
                if (TERMS >= 2) {
                    ldm4(r4, sBl + swz(rB, cl));
                    bl[2 * bt][0] = r4[0]; bl[2 * bt][1] = r4[2];
                    bl[2 * bt + 1][0] = r4[1]; bl[2 * bt + 1][1] = r4[3];
                }
            }
            #pragma unroll
            for (int mt = 0; mt < 4; mt++)
                #pragma unroll
                for (int nt = 0; nt < 8; nt++) {
                    mma16816(acc[mt][nt], ah[mt], bh[nt]);
                    if (TERMS >= 2) mma16816(acc[mt][nt], ah[mt], bl[nt]);
                    if (TERMS == 3) mma16816(acc[mt][nt], al[mt], bh[nt]);
                }
        }
    }
    __syncthreads();
}

// ---------------- symmetric Gram, triu-packed output ----------------
template<int TERMS>
__global__ __launch_bounds__(128, 2)
void k_gram_t(const __half* __restrict__ Xhi, const __half* __restrict__ Xlo,
              int ldk, int kIters, float* __restrict__ out) {
    extern __shared__ __half sm[];
    int p = blockIdx.x;
    int ti = 0, rem = 32;
    while (p >= rem) { p -= rem; rem--; ti++; }
    int tj = ti + p;
    const int i0 = ti * GBM, j0 = tj * GBM;

    int t = threadIdx.x;
    float acc[4][8][4];
    #pragma unroll
    for (int mt = 0; mt < 4; mt++)
        #pragma unroll
        for (int nt = 0; nt < 8; nt++)
            #pragma unroll
            for (int e = 0; e < 4; e++) acc[mt][nt][e] = 0.f;

    gemm_core<1, TERMS>(Xhi, Xlo, Xhi, Xlo, i0, j0, ldk, ldk, kIters, sm, t, acc);

    int lane = t & 31, wid = t >> 5;
    int wm = wid & 1, wn = wid >> 1;
    int r = lane >> 2, cp = (lane & 3) * 2;
    #pragma unroll
    for (int mt = 0; mt < 4; mt++) {
        #pragma unroll
        for (int h = 0; h < 2; h++) {
            int i = i0 + wm * 64 + mt * 16 + r + h * 8;
            int base = i * (8191 - i) / 2 - i - 1;
            #pragma unroll
            for (int nt = 0; nt < 8; nt++) {
                int j = j0 + wn * 64 + nt * 8 + cp;
                if (j > i)     out[base + j]     = acc[mt][nt][2 * h + 0];
                if (j + 1 > i) out[base + j + 1] = acc[mt][nt][2 * h + 1];
            }
        }
    }
}

// ---------------- conv GEMM: implicit im2col; MODE 0: bias; MODE 1: bias+tanh -> dst & out2 ----------------
template<int LA, int MODE, int TERMS>
__global__ __launch_bounds__(128, 2)
void k_conv_gemm(const __half* __restrict__ Ah, const __half* __restrict__ Al,
                 const __half* __restrict__ Bh, const __half* __restrict__ Bl,
                 int kIters, int bwA, int bwB, int Cout,
                 const float* __restrict__ bias, float* __restrict__ dst, float* __restrict__ out2) {
    extern __shared__ __half sm[];
    const int n0 = blockIdx.x * GBM, m0 = blockIdx.y * GBM;

    int t = threadIdx.x;
    float acc[4][8][4];
    #pragma unroll
    for (int mt = 0; mt < 4; mt++)
        #pragma unroll
        for (int nt = 0; nt < 8; nt++)
            #pragma unroll
            for (int e = 0; e < 4; e++) acc[mt][nt][e] = 0.f;

    gemm_core<LA, TERMS>(Ah, Al, Bh, Bl, m0, n0, bwA, bwB, kIters, sm, t, acc);

    int lane = t & 31, wid = t >> 5;
    int wm = wid & 1, wn = wid >> 1;
    int r = lane >> 2, cp = (lane & 3) * 2;
    #pragma unroll
    for (int mt = 0; mt < 4; mt++) {
        #pragma unroll
        for (int h = 0; h < 2; h++) {
            int m = m0 + wm * 64 + mt * 16 + r + h * 8;
            #pragma unroll
            for (int nt = 0; nt < 8; nt++) {
                int n = n0 + wn * 64 + nt * 8 + cp;
                float a0 = acc[mt][nt][2 * h + 0];
                float a1 = acc[mt][nt][2 * h + 1];
                if (MODE == 0) {
                    if (n < Cout)     dst[(size_t)m * Cout + n]     = a0 + bias[n];
                    if (n + 1 < Cout) dst[(size_t)m * Cout + n + 1] = a1 + bias[n + 1];
                } else {
                    if (n < Cout) {
                        float v = tanhf(a0 + bias[n]);
                        dst[(size_t)m * Cout + n] = v;
                        out2[(size_t)m * Cout + n] = v;
                    }
                    if (n + 1 < Cout) {
                        float v = tanhf(a1 + bias[n + 1]);
                        dst[(size_t)m * Cout + n + 1] = v;
                        out2[(size_t)m * Cout + n + 1] = v;
                    }
                }
            }
        }
    }
}

// ---------------- launch ----------------
extern "C" void kernel_launch(void* const* d_in, const int* in_sizes, int n_in,
                              void* d_out, int out_size) {
    const int*   x   = (const int*)  d_in[0];
    const float* emb = (const float*)d_in[1];
    const float* w1  = (const float*)d_in[2];
    const float* b1  = (const float*)d_in[3];
    const float* w2  = (const float*)d_in[4];
    const float* b2  = (const float*)d_in[5];
    const float* w3  = (const float*)d_in[6];
    const float* b3  = (const float*)d_in[7];
    const float* g1  = (const float*)d_in[8];
    const float* be1 = (const float*)d_in[9];
    const float* g2  = (const float*)d_in[10];
    const float* be2 = (const float*)d_in[11];
    float* out = (float*)d_out;

    const int smem1 = GSTAGES * 2 * MSZ * 2;   // TERMS=1: 49152
    const int smem3 = GSTAGES * 4 * MSZ * 2;   // TERMS=3: 98304
    cudaFuncSetAttribute(k_gram_t<1>,           cudaFuncAttributeMaxDynamicSharedMemorySize, smem1);
    cudaFuncSetAttribute(k_gram_t<3>,           cudaFuncAttributeMaxDynamicSharedMemorySize, smem3);
    cudaFuncSetAttribute(k_conv_gemm<13,0,1>,   cudaFuncAttributeMaxDynamicSharedMemorySize, smem1);
    cudaFuncSetAttribute(k_conv_gemm<5,0,1>,    cudaFuncAttributeMaxDynamicSharedMemorySize, smem1);
    cudaFuncSetAttribute(k_conv_gemm<1,1,3>,    cudaFuncAttributeMaxDynamicSharedMemorySize, smem3);

    __half *eh, *w1h, *w2h, *w3h, *w3l;
    __half *h1h, *h2h, *h2l, *fh, *fl;
    float *h1p, *h2p, *finp, *m1p, *i1p, *m2p, *i2p;
    cudaGetSymbolAddress((void**)&eh,  g_Eh);
    cudaGetSymbolAddress((void**)&w1h, g_W1h);
    cudaGetSymbolAddress((void**)&w2h, g_W2h);
    cudaGetSymbolAddress((void**)&w3h, g_W3h);
    cudaGetSymbolAddress((void**)&w3l, g_W3l);
    cudaGetSymbolAddress((void**)&h1h, g_h1h);
    cudaGetSymbolAddress((void**)&h2h, g_h2h);
    cudaGetSymbolAddress((void**)&h2l, g_h2l);
    cudaGetSymbolAddress((void**)&fh,  g_Fnh);
    cudaGetSymbolAddress((void**)&fl,  g_Fnl);
    cudaGetSymbolAddress((void**)&h1p, g_h1);
    cudaGetSymbolAddress((void**)&h2p, g_h2);
    cudaGetSymbolAddress((void**)&finp, g_final);
    cudaGetSymbolAddress((void**)&m1p, g_mean1);
    cudaGetSymbolAddress((void**)&i1p, g_istd1);
    cudaGetSymbolAddress((void**)&m2p, g_mean2);
    cudaGetSymbolAddress((void**)&i2p, g_istd2);

    cudaStream_t s2;
    cudaStreamCreateWithFlags(&s2, cudaStreamNonBlocking);
    cudaEvent_t evPrep, evGather, evJoin;
    cudaEventCreateWithFlags(&evPrep,   cudaEventDisableTiming);
    cudaEventCreateWithFlags(&evGather, cudaEventDisableTiming);
    cudaEventCreateWithFlags(&evJoin,   cudaEventDisableTiming);

    // ---- prologue: scales+gather on main; prep_w+padzero concurrently on s2 ----
    cudaEventRecord(evPrep, 0);              // fork point for s2 prologue
    cudaStreamWaitEvent(s2, evPrep, 0);
    k_prep_w<<<1024, 256, 0, s2>>>(w1, w2, w3);
    k_padzero<<<16, 256, 0, s2>>>();
    cudaEventRecord(evPrep, s2);             // prep+pads done

    k_scales<<<(VOCAB * 32 + 255) / 256, 256>>>(emb);
    k_gather<<<BATCH, 256>>>(x, emb);
    cudaEventRecord(evGather, 0);            // E_T ready

    // s2: big input Gram (needs gather + padzero; prep already on s2)
    cudaStreamWaitEvent(s2, evGather, 0);
    k_gram_t<1><<<528, 128, smem1, s2>>>(eh, eh, BW_E, BW_E / GBK, out + HOUT);
    cudaEventRecord(evJoin, s2);

    // main: conv chain (needs prep_w + padzero from s2)
    cudaStreamWaitEvent(0, evPrep, 0);
    {
        dim3 g(3, M1 / GBM);
        k_conv_gemm<13,0,1><<<g, 128, smem1>>>(eh, eh, w1h, w1h, (K1 + GBK - 1) / GBK, BW_E, K1, C1, b1, h1p, nullptr);
    }
    k_bnstat_p<<<dim3(10, 32), 256>>>(h1p, M1, C1);
    k_bnstat_r<<<2, 256>>>(C1, 1.f / M1, m1p, i1p);
    k_bnapply<<<2048, 256>>>(h1p, h1h, nullptr, m1p, i1p, g1, be1, M1, C1, L1o, 4);

    {
        dim3 g(5, M2 / GBM);
        k_conv_gemm<5,0,1><<<g, 128, smem1>>>(h1h, h1h, w2h, w2h, (K1 + GBK - 1) / GBK, BW_H1, K1, C2, b2, h2p, nullptr);
    }
    k_bnstat_p<<<dim3(19, 32), 256>>>(h2p, M2, C2);
    k_bnstat_r<<<3, 256>>>(C2, 1.f / M2, m2p, i2p);
    k_bnapply<<<2048, 256>>>(h2p, h2h, h2l, m2p, i2p, g2, be2, M2, C2, L2o, 8);

    {
        dim3 g(1, BATCH / GBM);
        k_conv_gemm<1,1,3><<<g, 128, smem3>>>(h2h, h2l, w3h, w3l, K3 / GBK, BW_H2, K3, C3, b3, finp, out);
    }
    k_norm<<<BATCH * 32 / 256, 256>>>();

    // hidden Gram: 3-term 128-tiles on main stream
    k_gram_t<3><<<528, 128, smem3>>>(fh, fl, KPAD_F, KPAD_F / GBK, out + HOUT + NPAIRS);

    // ---- join side stream ----
    cudaStreamWaitEvent(0, evJoin, 0);

    cudaEventDestroy(evPrep);
    cudaEventDestroy(evGather);
    cudaEventDestroy(evJoin);
    cudaStreamDestroy(s2);
}